// round 13
// baseline (speedup 1.0000x reference)
#include <cuda_runtime.h>
#include <stdint.h>
#include <math.h>

#define Bx 256
#define Sx 256
#define Ex 300
#define Hx 300
#define G4 1200     // 4*H
#define Cc 600      // 2*H channels
#define Mx 65536    // B*S
#define KCONV 1800  // 3*Cc

// ---------------- scratch (__device__ globals; zero-init at load) -------------
__device__ float d_xg_f[(size_t)Mx * G4];
__device__ float d_xg_b[(size_t)Mx * G4];
__device__ float d_to[(size_t)Mx * Cc];
// frag-major h ping-pong: [buf][group][152 chunks][128]  (152*128 = 19456)
__device__ float d_hf[2 * 8 * 19456];
__device__ float d_Whhf_t[Hx * G4];             // [k][j*4+g]
__device__ float d_Whhb_t[Hx * G4];
// fused input weights, tf32, fragment-major: [38 slabs][150 pairs][128]
__device__ float d_Wfrag[38 * 150 * 128];
__device__ float d_bif[G4];
__device__ float d_bib[G4];
__device__ float d_cw1[KCONV * Cc];
__device__ float d_cw2[KCONV * Cc];
__device__ float d_pw[Mx];
__device__ int   d_L[Bx], d_asp[Bx], d_left[Bx];
__device__ float d_ca[512 * KCONV];
__device__ float d_x2row[512 * Cc];
__device__ float d_rowscale[512];
__device__ float d_v[Bx * Cc];
__device__ float d_logits[Mx];
__device__ unsigned d_barg[8 * 32];             // one counter per 128B line

__device__ __forceinline__ float to_tf32(float x) {
    uint32_t r;
    asm("cvt.rna.tf32.f32 %0, %1;" : "=r"(r) : "f"(x));
    return __uint_as_float(r);
}
__device__ __forceinline__ float fsig(float x) {
    return __fdividef(1.f, 1.f + __expf(-x));
}
__device__ __forceinline__ float ftanh(float x) {
    return __fdividef(2.f, 1.f + __expf(-2.f * x)) - 1.f;
}
__device__ __forceinline__ void bar_release_add(unsigned* p) {
    asm volatile("red.add.release.gpu.u32 [%0], 1;" :: "l"(p) : "memory");
}
__device__ __forceinline__ unsigned bar_acquire_ld(unsigned* p) {
    unsigned v;
    asm volatile("ld.acquire.gpu.u32 %0, [%1];" : "=r"(v) : "l"(p) : "memory");
    return v;
}

// ---------------- meta ---------------------------------------------------------
__global__ void k_meta(const int* __restrict__ cat, const int* __restrict__ aspi,
                       const int* __restrict__ lefti) {
    __shared__ int s[3];
    int b = blockIdx.x, t = threadIdx.x;
    if (t < 3) s[t] = 0;
    __syncthreads();
    if (cat[b * Sx + t] != 0) atomicAdd(&s[0], 1);
    if (t < 16 && aspi[b * 16 + t] != 0) atomicAdd(&s[1], 1);
    if (t < 128 && lefti[b * 128 + t] != 0) atomicAdd(&s[2], 1);
    __syncthreads();
    int L = s[0], A = s[1], Le = s[2];
    if (t == 0) { d_L[b] = L; d_asp[b] = A; d_left[b] = Le; }
    float na = (float)(L - A);
    int right = Le + A - 1;
    float w;
    if (t < Le)           w = 1.0f - (float)(Le - t) / na;
    else if (t <= right)  w = 0.0f;
    else if (t < L)       w = 1.0f - (float)(t - right) / na;
    else                  w = 0.0f;
    d_pw[b * Sx + t] = w;
}

// ---------------- zero h buffers + group barrier counters ----------------------
__global__ void k_zero() {
    int stride = gridDim.x * blockDim.x;
    int tid0 = blockIdx.x * blockDim.x + threadIdx.x;
    for (int i = tid0; i < 2 * 8 * 19456; i += stride) d_hf[i] = 0.f;
    if (tid0 < 8 * 32) d_barg[tid0] = 0u;
}

// ---------------- weight reshapes ----------------------------------------------
__global__ void k_prep(const float* __restrict__ Wihf, const float* __restrict__ Whhf,
                       const float* __restrict__ bf,
                       const float* __restrict__ Wihb, const float* __restrict__ Whhb,
                       const float* __restrict__ bbv,
                       const float* __restrict__ c1w, const float* __restrict__ c2w) {
    int stride = gridDim.x * blockDim.x;
    int tid0 = blockIdx.x * blockDim.x + threadIdx.x;
    // recurrent weights -> [k][j*4+g]
    for (int idx = tid0; idx < Ex * G4; idx += stride) {
        int k = idx / G4, col = idx - k * G4;
        int j = col >> 2, g = col & 3;
        int src = (g * Hx + j) * Ex + k;   // Ex == Hx
        d_Whhf_t[idx] = Whhf[src];
        d_Whhb_t[idx] = Whhb[src];
    }
    // fused input weights -> tf32 fragment-major d_Wfrag
    for (int idx = tid0; idx < 38 * 150 * 128; idx += stride) {
        int kb = idx / 19200;
        int rem = idx - kb * 19200;
        int np = rem >> 7;
        int li = rem & 127;
        int l = li >> 2, slot = li & 3;
        int atom = np * 2 + (slot >> 1);
        int col = atom * 8 + (l >> 2);
        int k = kb * 8 + (l & 3) + ((slot & 1) << 2);
        float v = 0.f;
        if (k < Ex) {
            int colp = (col < G4) ? col : col - G4;
            const float* W = (col < G4) ? Wihf : Wihb;
            int j = colp >> 2, g = colp & 3;
            v = W[(g * Hx + j) * Ex + k];
        }
        d_Wfrag[idx] = to_tf32(v);
    }
    for (int idx = tid0; idx < G4; idx += stride) {
        int j = idx >> 2, g = idx & 3;
        d_bif[idx] = bf[g * Hx + j];
        d_bib[idx] = bbv[g * Hx + j];
    }
    for (int idx = tid0; idx < KCONV * Cc; idx += stride) {
        int o = idx % Cc, r = idx / Cc;
        int kk = r / Cc, i = r - kk * Cc;
        size_t src = (size_t)o * KCONV + i * 3 + kk;
        d_cw1[idx] = c1w[src];
        d_cw2[idx] = c2w[src];
    }
}

// ---------------- xg GEMM: A smem-staged, B fragment-major from L2 -------------
#define LDSW 136
__global__ __launch_bounds__(256, 2)
void xg_gemm(const int* __restrict__ cat, const float* __restrict__ emb) {
    __shared__ float As[2][16][LDSW];

    int tid = threadIdx.x;
    int lane = tid & 31, wid = tid >> 5;
    int wm = (wid & 1) * 64;
    int wn = (wid >> 1) * 32;
    int m0 = blockIdx.y * 128, n0 = blockIdx.x * 128;
    int npg = (n0 + wn) >> 4;

    size_t abase[2]; int arow[2], akq[2];
#pragma unroll
    for (int q = 0; q < 2; q++) {
        int pos = tid + 256 * q;
        arow[q] = pos >> 2;
        akq[q]  = (pos & 3) * 4;
        abase[q] = (size_t)cat[m0 + arow[q]] * Ex;
    }

    float4 ra[2];
    auto loadA = [&](int k0) {
#pragma unroll
        for (int q = 0; q < 2; q++) {
            int k = k0 + akq[q];
            ra[q] = (k < Ex) ? *(const float4*)(emb + abase[q] + k)
                             : make_float4(0.f, 0.f, 0.f, 0.f);
        }
    };
    auto storeA = [&](int s) {
#pragma unroll
        for (int q = 0; q < 2; q++) {
            As[s][akq[q] + 0][arow[q]] = to_tf32(ra[q].x);
            As[s][akq[q] + 1][arow[q]] = to_tf32(ra[q].y);
            As[s][akq[q] + 2][arow[q]] = to_tf32(ra[q].z);
            As[s][akq[q] + 3][arow[q]] = to_tf32(ra[q].w);
        }
    };

    float4 breg[2][2];
    auto loadB = [&](int kbg, float4 bp[2]) {
#pragma unroll
        for (int p = 0; p < 2; p++) {
            int np = npg + p;
            bp[p] = (np < 150)
                ? __ldg((const float4*)(d_Wfrag + ((size_t)kbg * 150 + np) * 128 + lane * 4))
                : make_float4(0.f, 0.f, 0.f, 0.f);
        }
    };

    float acc[4][4][4];
#pragma unroll
    for (int i = 0; i < 4; i++)
#pragma unroll
        for (int j = 0; j < 4; j++)
#pragma unroll
            for (int q = 0; q < 4; q++) acc[i][j][q] = 0.f;

    int r = lane >> 2, c = lane & 3;

    loadA(0); storeA(0);
    loadB(0, breg[0]);
    __syncthreads();

    for (int it = 0; it < 19; it++) {
        if (it + 1 < 19) loadA((it + 1) * 16);
#pragma unroll
        for (int ks = 0; ks < 2; ks++) {
            int kbg = it * 2 + ks;
            if (kbg + 1 < 38) loadB(kbg + 1, breg[(kbg + 1) & 1]);
            int kb = ks * 8;
            int s = it & 1;
            uint32_t af[4][4];
#pragma unroll
            for (int mt = 0; mt < 4; mt++) {
                int mb = wm + mt * 16 + r;
                af[mt][0] = __float_as_uint(As[s][kb + c][mb]);
                af[mt][1] = __float_as_uint(As[s][kb + c][mb + 8]);
                af[mt][2] = __float_as_uint(As[s][kb + c + 4][mb]);
                af[mt][3] = __float_as_uint(As[s][kb + c + 4][mb + 8]);
            }
            float4* bp = breg[kbg & 1];
            uint32_t bf[4][2];
#pragma unroll
            for (int p = 0; p < 2; p++) {
                bf[p * 2 + 0][0] = __float_as_uint(bp[p].x);
                bf[p * 2 + 0][1] = __float_as_uint(bp[p].y);
                bf[p * 2 + 1][0] = __float_as_uint(bp[p].z);
                bf[p * 2 + 1][1] = __float_as_uint(bp[p].w);
            }
#pragma unroll
            for (int mt = 0; mt < 4; mt++)
#pragma unroll
                for (int nt = 0; nt < 4; nt++) {
                    asm volatile(
                        "mma.sync.aligned.m16n8k8.row.col.f32.tf32.tf32.f32 "
                        "{%0,%1,%2,%3}, {%4,%5,%6,%7}, {%8,%9}, {%0,%1,%2,%3};"
                        : "+f"(acc[mt][nt][0]), "+f"(acc[mt][nt][1]),
                          "+f"(acc[mt][nt][2]), "+f"(acc[mt][nt][3])
                        : "r"(af[mt][0]), "r"(af[mt][1]), "r"(af[mt][2]), "r"(af[mt][3]),
                          "r"(bf[nt][0]), "r"(bf[nt][1]));
                }
        }
        if (it + 1 < 19) storeA((it + 1) & 1);
        __syncthreads();
    }

#pragma unroll
    for (int mt = 0; mt < 4; mt++) {
#pragma unroll
        for (int j2 = 0; j2 < 2; j2++) {
            int m = m0 + wm + mt * 16 + r + j2 * 8;
#pragma unroll
            for (int nt = 0; nt < 4; nt++) {
                int n = n0 + wn + (nt >> 1) * 16 + (nt & 1) * 8 + c * 2;
#pragma unroll
                for (int jj = 0; jj < 2; jj++) {
                    int nn = n + jj;
                    float v = acc[mt][nt][j2 * 2 + jj];
                    if (nn < G4)
                        d_xg_f[(size_t)m * G4 + nn] = v + d_bif[nn];
                    else if (nn < 2400)
                        d_xg_b[(size_t)m * G4 + (nn - G4)] = v + d_bib[nn - G4];
                }
            }
        }
    }
}

// ---------------- conv1 GEMM (proven template) ---------------------------------
__global__ __launch_bounds__(256, 2)
void conv_gemm(const float* __restrict__ extbias) {
    constexpr int N = Cc, K = KCONV, BK = 16;
    const float* A = d_ca;
    const float* Bw = d_cw1;
    float* Cout = d_x2row;

    __shared__ float As[2][BK][LDSW];
    __shared__ float Bs[2][BK][LDSW];

    int tid = threadIdx.x;
    int lane = tid & 31, wid = tid >> 5;
    int wm = (wid & 1) * 64;
    int wn = (wid >> 1) * 32;
    int m0 = blockIdx.y * 128, n0 = blockIdx.x * 128;

    size_t abase[2]; int arow[2], akq[2];
    int bkr[2], bnq[2];
#pragma unroll
    for (int q = 0; q < 2; q++) {
        int pos = tid + 256 * q;
        arow[q] = pos >> 2;
        akq[q]  = (pos & 3) * 4;
        abase[q] = (size_t)(m0 + arow[q]) * K;
        bkr[q] = pos >> 5;
        bnq[q] = (pos & 31) * 4;
    }

    float4 ra[2], rb[2];
    auto load_tiles = [&](int k0) {
#pragma unroll
        for (int q = 0; q < 2; q++) {
            int k = k0 + akq[q];
            ra[q] = (k < K) ? *(const float4*)(A + abase[q] + k)
                            : make_float4(0.f, 0.f, 0.f, 0.f);
            int kb = k0 + bkr[q], n = n0 + bnq[q];
            rb[q] = (kb < K && n < N) ? *(const float4*)(Bw + (size_t)kb * N + n)
                                      : make_float4(0.f, 0.f, 0.f, 0.f);
        }
    };
    auto store_tiles = [&](int s) {
#pragma unroll
        for (int q = 0; q < 2; q++) {
            As[s][akq[q] + 0][arow[q]] = to_tf32(ra[q].x);
            As[s][akq[q] + 1][arow[q]] = to_tf32(ra[q].y);
            As[s][akq[q] + 2][arow[q]] = to_tf32(ra[q].z);
            As[s][akq[q] + 3][arow[q]] = to_tf32(ra[q].w);
            Bs[s][bkr[q]][bnq[q] + 0] = to_tf32(rb[q].x);
            Bs[s][bkr[q]][bnq[q] + 1] = to_tf32(rb[q].y);
            Bs[s][bkr[q]][bnq[q] + 2] = to_tf32(rb[q].z);
            Bs[s][bkr[q]][bnq[q] + 3] = to_tf32(rb[q].w);
        }
    };

    float acc[4][4][4];
#pragma unroll
    for (int i = 0; i < 4; i++)
#pragma unroll
        for (int j = 0; j < 4; j++)
#pragma unroll
            for (int q = 0; q < 4; q++) acc[i][j][q] = 0.f;

    int r = lane >> 2, c = lane & 3;

    auto compute = [&](int s) {
#pragma unroll
        for (int ks = 0; ks < 2; ks++) {
            int kb = ks * 8;
            uint32_t af[4][4], bf[4][2];
#pragma unroll
            for (int mt = 0; mt < 4; mt++) {
                int mb = wm + mt * 16 + r;
                af[mt][0] = __float_as_uint(As[s][kb + c][mb]);
                af[mt][1] = __float_as_uint(As[s][kb + c][mb + 8]);
                af[mt][2] = __float_as_uint(As[s][kb + c + 4][mb]);
                af[mt][3] = __float_as_uint(As[s][kb + c + 4][mb + 8]);
            }
#pragma unroll
            for (int nt = 0; nt < 4; nt++) {
                int nb = wn + nt * 8 + r;
                bf[nt][0] = __float_as_uint(Bs[s][kb + c][nb]);
                bf[nt][1] = __float_as_uint(Bs[s][kb + c + 4][nb]);
            }
#pragma unroll
            for (int mt = 0; mt < 4; mt++)
#pragma unroll
                for (int nt = 0; nt < 4; nt++) {
                    asm volatile(
                        "mma.sync.aligned.m16n8k8.row.col.f32.tf32.tf32.f32 "
                        "{%0,%1,%2,%3}, {%4,%5,%6,%7}, {%8,%9}, {%0,%1,%2,%3};"
                        : "+f"(acc[mt][nt][0]), "+f"(acc[mt][nt][1]),
                          "+f"(acc[mt][nt][2]), "+f"(acc[mt][nt][3])
                        : "r"(af[mt][0]), "r"(af[mt][1]), "r"(af[mt][2]), "r"(af[mt][3]),
                          "r"(bf[nt][0]), "r"(bf[nt][1]));
                }
        }
    };

    constexpr int NK = (K + BK - 1) / BK;
    load_tiles(0);
    store_tiles(0);
    __syncthreads();
    for (int it = 0; it < NK; it++) {
        if (it + 1 < NK) load_tiles((it + 1) * BK);
        compute(it & 1);
        if (it + 1 < NK) store_tiles((it + 1) & 1);
        __syncthreads();
    }

#pragma unroll
    for (int mt = 0; mt < 4; mt++) {
#pragma unroll
        for (int j2 = 0; j2 < 2; j2++) {
            int m = m0 + wm + mt * 16 + r + j2 * 8;
            float scl = d_rowscale[m];
#pragma unroll
            for (int nt = 0; nt < 4; nt++) {
                int n = n0 + wn + nt * 8 + c * 2;
#pragma unroll
                for (int jj = 0; jj < 2; jj++) {
                    int nn = n + jj;
                    if (nn < N) {
                        float v = acc[mt][nt][j2 * 2 + jj] + extbias[nn];
                        v = fmaxf(v, 0.f) * scl;
                        Cout[(size_t)m * N + nn] = v;
                    }
                }
            }
        }
    }
}

// ---------------- persistent LSTM v6: 512 threads (4 warps/SMSP) ---------------
// 8 row-groups(64 rows) x 13 col-tiles(96 cols) = 104 blocks, 512 threads.
// 16 warps = 4 m-warps x 4 n-warps; each warp: 3 atoms (24 gate-cols).
#define AVCH 132
#define WS3_FLOATS (38 * 6 * AVCH)   // 30096
#define AV3_FLOATS (38 * 4 * AVCH)   // 20064
#define LSTM3_SMEM ((WS3_FLOATS + AV3_FLOATS) * 4)   // 200640

__global__ __launch_bounds__(512, 1)
void lstm_persist6() {
    extern __shared__ float sm[];
    float* Ws = sm;                  // [kb*6+np][132]  (np = atom-pair 0..5)
    float* Av = sm + WS3_FLOATS;     // [kb*4+mt][132]

    const int tid = threadIdx.x;
    const int lane = tid & 31, wid = tid >> 5;
    const int rt = blockIdx.x / 13, ct = blockIdx.x % 13;
    const int row0 = rt * 64, col0 = ct * 96;
    const bool bwd = (row0 >= 256);
    const float* Wt = bwd ? d_Whhb_t : d_Whhf_t;
    const float* xg = bwd ? d_xg_b : d_xg_f;

    // one-time: W tile -> frag-major smem (tf32)
    for (int idx = tid; idx < 38 * 6 * 128; idx += 512) {
        int kb = idx / (6 * 128);
        int rem = idx - kb * 6 * 128;
        int np = rem >> 7;
        int li = rem & 127;
        int l = li >> 2, slot = li & 3;
        int atom = np * 2 + (slot >> 1);
        int col = col0 + atom * 8 + (l >> 2);
        int k = kb * 8 + (l & 3) + (slot & 1) * 4;
        float v = (k < Hx && col < G4) ? Wt[(size_t)k * G4 + col] : 0.f;
        Ws[(kb * 6 + np) * AVCH + li] = to_tf32(v);
    }
    __syncthreads();

    const int r = lane >> 2, c = lane & 3;
    const int mtw = wid & 3;          // 4 m-warps (16 rows each)
    const int nw  = wid >> 2;         // 4 n-warps (24 cols = 3 atoms each)
    const int pA  = (3 * nw) >> 1;    // first atom-pair chunk this warp reads
    const bool nodd = (nw & 1);
    const bool evenc = ((c & 1) == 0);
    const int oddc = evenc ? 0 : 1;
    const int cpair = c >> 1;
    const int row_g = row0 + mtw * 16 + r + (evenc ? 0 : 8);
    const int b = row_g & 255;
    const int Lb = d_L[b];
    unsigned* barp = &d_barg[rt * 32];

    int jidx[3];
#pragma unroll
    for (int a = 0; a < 3; a++)
        jidx[a] = ((col0 + (nw * 3 + a) * 8) >> 2) + cpair;

    float cst[3] = {0.f, 0.f, 0.f};

    for (int t = 0; t < Sx; t++) {
        const float* src = d_hf + ((size_t)((t & 1) * 8 + rt)) * 19456;
        float*       dstg = d_hf + ((size_t)(((t + 1) & 1) * 8 + rt)) * 19456;

        // ---- prefetch xg row fragments for this step ----
        int tsrc = bwd ? ((t < Lb) ? (Lb - 1 - t) : t) : t;
        int pos  = bwd ? tsrc : t;
        const float* xgrow = xg + ((size_t)(b * Sx + tsrc)) * G4;
        float4 xv[3];
#pragma unroll
        for (int a = 0; a < 3; a++)
            xv[a] = (jidx[a] < Hx) ? __ldg((const float4*)(xgrow + jidx[a] * 4))
                                   : make_float4(0.f, 0.f, 0.f, 0.f);

        // ---- stage h tile: straight vectorized copy ----
#pragma unroll
        for (int q = 0; q < 10; q++) {
            int f = tid + 512 * q;
            if (f < 4864) {
                int chunk = f >> 5, off = f & 31;
                float4 v = __ldcg((const float4*)(src + (size_t)f * 4));
                *(float4*)(Av + chunk * AVCH + off * 4) = v;
            }
        }
        __syncthreads();

        // ---- MMA inner loop: 38 K-blocks, 3 MMAs each ----
        float acc[3][4];
#pragma unroll
        for (int a = 0; a < 3; a++)
#pragma unroll
            for (int q = 0; q < 4; q++) acc[a][q] = 0.f;

#pragma unroll 2
        for (int kb = 0; kb < 38; kb++) {
            float4 a4 = *(const float4*)(Av + (kb * 4 + mtw) * AVCH
                                         + (((lane + kb) & 31) << 2));
            uint32_t af0 = __float_as_uint(a4.x), af1 = __float_as_uint(a4.y);
            uint32_t af2 = __float_as_uint(a4.z), af3 = __float_as_uint(a4.w);
            float4 B0 = *(const float4*)(Ws + (kb * 6 + pA) * AVCH + (lane << 2));
            float4 B1 = *(const float4*)(Ws + (kb * 6 + pA + 1) * AVCH + (lane << 2));
            uint32_t bf[3][2];
            if (nodd) {
                bf[0][0] = __float_as_uint(B0.z); bf[0][1] = __float_as_uint(B0.w);
                bf[1][0] = __float_as_uint(B1.x); bf[1][1] = __float_as_uint(B1.y);
                bf[2][0] = __float_as_uint(B1.z); bf[2][1] = __float_as_uint(B1.w);
            } else {
                bf[0][0] = __float_as_uint(B0.x); bf[0][1] = __float_as_uint(B0.y);
                bf[1][0] = __float_as_uint(B0.z); bf[1][1] = __float_as_uint(B0.w);
                bf[2][0] = __float_as_uint(B1.x); bf[2][1] = __float_as_uint(B1.y);
            }
#pragma unroll
            for (int a = 0; a < 3; a++) {
                asm volatile(
                    "mma.sync.aligned.m16n8k8.row.col.f32.tf32.tf32.f32 "
                    "{%0,%1,%2,%3}, {%4,%5,%6,%7}, {%8,%9}, {%0,%1,%2,%3};"
                    : "+f"(acc[a][0]), "+f"(acc[a][1]),
                      "+f"(acc[a][2]), "+f"(acc[a][3])
                    : "r"(af0), "r"(af1), "r"(af2), "r"(af3),
                      "r"(bf[a][0]), "r"(bf[a][1]));
            }
        }

        // ---- epilogue ----
        float hvals[3];
#pragma unroll
        for (int a = 0; a < 3; a++) {
            float d0 = acc[a][0], d1 = acc[a][1], d2 = acc[a][2], d3 = acc[a][3];
            float x0 = __shfl_xor_sync(0xFFFFFFFFu, evenc ? d2 : d0, 1);
            float x1 = __shfl_xor_sync(0xFFFFFFFFu, evenc ? d3 : d1, 1);
            float gi = evenc ? d0 : x0;
            float gf = evenc ? d1 : x1;
            float gg = evenc ? x0 : d2;
            float go = evenc ? x1 : d3;
            if (jidx[a] < Hx) {
                gi += xv[a].x; gf += xv[a].y; gg += xv[a].z; go += xv[a].w;
                float si = fsig(gi);
                float sf = fsig(gf);
                float so = fsig(go);
                float cn = sf * cst[a] + si * ftanh(gg);
                cst[a] = cn;
                hvals[a] = so * ftanh(cn);
            } else hvals[a] = 0.f;
        }
        size_t tbase = ((size_t)(b * Sx + pos)) * Cc + (bwd ? Hx : 0);
        float mask = (t < Lb) ? 1.f : 0.f;
        bool last = (t == Sx - 1);
#pragma unroll
        for (int a = 0; a < 3; a++) {
            int j = jidx[a];
            if (j < Hx) {
                d_to[tbase + j] = hvals[a] * mask;
                if (!last) {
                    int kb = j >> 3;
                    int slot = (((j >> 2) & 1) << 1) + oddc;
                    int lp = (r * 4 + (j & 3) + kb) & 31;
                    dstg[(kb * 4 + mtw) * 128 + lp * 4 + slot] = to_tf32(hvals[a]);
                }
            }
        }

        // ---- per-group barrier (13 blocks), release/acquire, padded line ----
        if (!last) {
            __syncthreads();
            if (tid == 0) {
                bar_release_add(barp);
                unsigned target = 13u * (unsigned)(t + 1);
                while (bar_acquire_ld(barp) < target) __nanosleep(16);
            }
            __syncthreads();
        }
    }
}

// ---------------- gather conv1 input windows (2 rows per batch) -----------------
__global__ void k_gatherca() {
    int rr = blockIdx.x;
    int b = rr >> 1, side = rr & 1;
    int le = d_left[b];
    int rt = le + d_asp[b] - 1;
    int p = side ? (rt + 1) : (le - 1);
    bool valid = (p >= 0 && p < Sx);
    if (threadIdx.x == 0)
        d_rowscale[rr] = valid ? d_pw[b * Sx + p] : 0.f;
    for (int k = threadIdx.x; k < KCONV; k += blockDim.x) {
        int dk = k / Cc, i = k - dk * Cc;
        int prow = p - 1 + dk;
        float val = 0.f;
        if (valid && prow >= 0 && prow < Sx)
            val = d_to[((size_t)(b * Sx + prow)) * Cc + i] * d_pw[b * Sx + prow];
        d_ca[(size_t)rr * KCONV + k] = val;
    }
}

// ---------------- conv2 on the two nonzero rows + v ----------------------------
__global__ void k_vrow(const float* __restrict__ c2bias) {
    __shared__ float s0[Cc], s1[Cc];
    int b = blockIdx.x, tid = threadIdx.x;
    int a = d_asp[b];
    for (int i = tid; i < Cc; i += blockDim.x) {
        s0[i] = d_x2row[(size_t)(b * 2 + 0) * Cc + i];
        s1[i] = d_x2row[(size_t)(b * 2 + 1) * Cc + i];
    }
    __syncthreads();
    float acc0[3] = {0.f, 0.f, 0.f}, acc1[3] = {0.f, 0.f, 0.f};
    for (int i = 0; i < Cc; i++) {
        float a0 = s0[i], a1 = s1[i];
        const float* w0 = d_cw2 + (size_t)i * Cc;
        const float* w2 = d_cw2 + (size_t)(1200 + i) * Cc;
#pragma unroll
        for (int q = 0; q < 3; q++) {
            int o = tid + q * 256;
            if (o < Cc) {
                acc0[q] = fmaf(w0[o], a0, acc0[q]);
                acc1[q] = fmaf(w2[o], a1, acc1[q]);
            }
        }
    }
#pragma unroll
    for (int q = 0; q < 3; q++) {
        int o = tid + q * 256;
        if (o < Cc) {
            float bb = c2bias[o];
            float v;
            if (a == 1) {
                v = fmaxf(acc0[q] + acc1[q] + bb, 0.f);
            } else {
                v = fmaxf(acc0[q] + bb, 0.f) + fmaxf(acc1[q] + bb, 0.f)
                  + (float)(a - 2) * fmaxf(bb, 0.f);
            }
            d_v[b * Cc + o] = v;
        }
    }
}

// ---------------- logits -------------------------------------------------------
__global__ void k_logits() {
    int b = blockIdx.x;
    int w = threadIdx.x >> 5, lane = threadIdx.x & 31;
    int t = blockIdx.y * 8 + w;
    const float* vb = d_v + (size_t)b * Cc;
    const float* to = d_to + ((size_t)(b * Sx + t)) * Cc;
    float s = 0.f;
    for (int c = lane; c < Cc; c += 32) s = fmaf(vb[c], to[c], s);
#pragma unroll
    for (int o = 16; o; o >>= 1) s += __shfl_xor_sync(0xFFFFFFFFu, s, o);
    if (lane == 0) d_logits[b * Sx + t] = s;
}

// ---------------- softmax + feat + fc ------------------------------------------
__global__ void k_final(const float* __restrict__ fcw, const float* __restrict__ fcb,
                        float* __restrict__ out) {
    __shared__ float sred[256];
    __shared__ float salpha[256];
    __shared__ float feat[Cc];
    int b = blockIdx.x, t = threadIdx.x;
    float lg = d_logits[b * Sx + t];
    sred[t] = lg;
    __syncthreads();
    for (int o = 128; o; o >>= 1) { if (t < o) sred[t] = fmaxf(sred[t], sred[t + o]); __syncthreads(); }
    float mx = sred[0];
    __syncthreads();
    float e = expf(lg - mx);
    salpha[t] = e;
    sred[t] = e;
    __syncthreads();
    for (int o = 128; o; o >>= 1) { if (t < o) sred[t] += sred[t + o]; __syncthreads(); }
    float Z = sred[0];
    __syncthreads();
    for (int c = t; c < Cc; c += 256) {
        float f = 0.f;
        for (int tt = 0; tt < Sx; tt++)
            f = fmaf(salpha[tt], d_to[((size_t)(b * Sx + tt)) * Cc + c], f);
        feat[c] = f / Z;
    }
    __syncthreads();
    for (int p = 0; p < 3; p++) {
        float part = 0.f;
        for (int c = t; c < Cc; c += 256) part = fmaf(feat[c], fcw[p * Cc + c], part);
        sred[t] = part;
        __syncthreads();
        for (int o = 128; o; o >>= 1) { if (t < o) sred[t] += sred[t + o]; __syncthreads(); }
        if (t == 0) out[b * 3 + p] = sred[0] + fcb[p];
        __syncthreads();
    }
}

// ---------------- launch -------------------------------------------------------
extern "C" void kernel_launch(void* const* d_in, const int* in_sizes, int n_in,
                              void* d_out, int out_size) {
    (void)in_sizes; (void)n_in; (void)out_size;
    const int*   cat   = (const int*)d_in[0];
    const int*   aspi  = (const int*)d_in[1];
    const int*   lefti = (const int*)d_in[2];
    const float* emb   = (const float*)d_in[3];
    const float* Wihf  = (const float*)d_in[4];
    const float* Whhf  = (const float*)d_in[5];
    const float* bf    = (const float*)d_in[6];
    const float* Wihb  = (const float*)d_in[7];
    const float* Whhb  = (const float*)d_in[8];
    const float* bbv   = (const float*)d_in[9];
    const float* c1w   = (const float*)d_in[10];
    const float* c1b   = (const float*)d_in[11];
    const float* c2w   = (const float*)d_in[12];
    const float* c2b   = (const float*)d_in[13];
    const float* fcw   = (const float*)d_in[14];
    const float* fcb   = (const float*)d_in[15];
    float* out = (float*)d_out;

    cudaFuncSetAttribute(lstm_persist6, cudaFuncAttributeMaxDynamicSharedMemorySize,
                         LSTM3_SMEM);

    k_meta<<<Bx, 256>>>(cat, aspi, lefti);
    k_zero<<<512, 256>>>();
    k_prep<<<2048, 256>>>(Wihf, Whhf, bf, Wihb, Whhb, bbv, c1w, c2w);

    dim3 g1(19, 512);   // N=2400, M=65536
    xg_gemm<<<g1, 256>>>(cat, emb);

    lstm_persist6<<<104, 512, LSTM3_SMEM>>>();

    k_gatherca<<<512, 256>>>();
    dim3 g2(5, 4);      // N=600, M=512
    conv_gemm<<<g2, 256>>>(c1b);
    k_vrow<<<Bx, 256>>>(c2b);

    dim3 g3(Bx, 32);
    k_logits<<<g3, 256>>>();
    k_final<<<Bx, 256>>>(fcw, fcb, out);
}

// round 14
// speedup vs baseline: 1.0208x; 1.0208x over previous
#include <cuda_runtime.h>
#include <stdint.h>
#include <math.h>

#define Bx 256
#define Sx 256
#define Ex 300
#define Hx 300
#define G4 1200     // 4*H
#define Cc 600      // 2*H channels
#define Mx 65536    // B*S
#define KCONV 1800  // 3*Cc

// ---------------- scratch (__device__ globals; zero-init at load) -------------
__device__ float d_xg_f[(size_t)Mx * G4];
__device__ float d_xg_b[(size_t)Mx * G4];
__device__ float d_to[(size_t)Mx * Cc];
// frag-major h ping-pong: [buf][group][152 chunks][128]  (152*128 = 19456)
__device__ float d_hf[2 * 8 * 19456];
__device__ float d_Whhf_t[Hx * G4];             // [k][j*4+g]
__device__ float d_Whhb_t[Hx * G4];
// fused input weights, tf32, fragment-major: [38 slabs][150 pairs][128]
__device__ float d_Wfrag[38 * 150 * 128];
__device__ float d_bif[G4];
__device__ float d_bib[G4];
__device__ float d_cw1[KCONV * Cc];
__device__ float d_cw2[KCONV * Cc];
__device__ float d_pw[Mx];
__device__ int   d_L[Bx], d_asp[Bx], d_left[Bx];
__device__ float d_ca[512 * KCONV];
__device__ float d_x2row[512 * Cc];
__device__ float d_rowscale[512];
__device__ float d_v[Bx * Cc];
__device__ float d_logits[Mx];
__device__ unsigned d_barg[8 * 32];             // one counter per 128B line

__device__ __forceinline__ float to_tf32(float x) {
    uint32_t r;
    asm("cvt.rna.tf32.f32 %0, %1;" : "=r"(r) : "f"(x));
    return __uint_as_float(r);
}
__device__ __forceinline__ float fsig(float x) {
    return __fdividef(1.f, 1.f + __expf(-x));
}
__device__ __forceinline__ float ftanh(float x) {
    return __fdividef(2.f, 1.f + __expf(-2.f * x)) - 1.f;
}
__device__ __forceinline__ void bar_release_add(unsigned* p) {
    asm volatile("red.add.release.gpu.u32 [%0], 1;" :: "l"(p) : "memory");
}
__device__ __forceinline__ unsigned bar_acquire_ld(unsigned* p) {
    unsigned v;
    asm volatile("ld.acquire.gpu.u32 %0, [%1];" : "=r"(v) : "l"(p) : "memory");
    return v;
}

// ---------------- meta ---------------------------------------------------------
__global__ void k_meta(const int* __restrict__ cat, const int* __restrict__ aspi,
                       const int* __restrict__ lefti) {
    __shared__ int s[3];
    int b = blockIdx.x, t = threadIdx.x;
    if (t < 3) s[t] = 0;
    __syncthreads();
    if (cat[b * Sx + t] != 0) atomicAdd(&s[0], 1);
    if (t < 16 && aspi[b * 16 + t] != 0) atomicAdd(&s[1], 1);
    if (t < 128 && lefti[b * 128 + t] != 0) atomicAdd(&s[2], 1);
    __syncthreads();
    int L = s[0], A = s[1], Le = s[2];
    if (t == 0) { d_L[b] = L; d_asp[b] = A; d_left[b] = Le; }
    float na = (float)(L - A);
    int right = Le + A - 1;
    float w;
    if (t < Le)           w = 1.0f - (float)(Le - t) / na;
    else if (t <= right)  w = 0.0f;
    else if (t < L)       w = 1.0f - (float)(t - right) / na;
    else                  w = 0.0f;
    d_pw[b * Sx + t] = w;
}

// ---------------- zero h buffers + group barrier counters ----------------------
__global__ void k_zero() {
    int stride = gridDim.x * blockDim.x;
    int tid0 = blockIdx.x * blockDim.x + threadIdx.x;
    for (int i = tid0; i < 2 * 8 * 19456; i += stride) d_hf[i] = 0.f;
    if (tid0 < 8 * 32) d_barg[tid0] = 0u;
}

// ---------------- weight reshapes ----------------------------------------------
__global__ void k_prep(const float* __restrict__ Wihf, const float* __restrict__ Whhf,
                       const float* __restrict__ bf,
                       const float* __restrict__ Wihb, const float* __restrict__ Whhb,
                       const float* __restrict__ bbv,
                       const float* __restrict__ c1w, const float* __restrict__ c2w) {
    int stride = gridDim.x * blockDim.x;
    int tid0 = blockIdx.x * blockDim.x + threadIdx.x;
    // recurrent weights -> [k][j*4+g]
    for (int idx = tid0; idx < Ex * G4; idx += stride) {
        int k = idx / G4, col = idx - k * G4;
        int j = col >> 2, g = col & 3;
        int src = (g * Hx + j) * Ex + k;   // Ex == Hx
        d_Whhf_t[idx] = Whhf[src];
        d_Whhb_t[idx] = Whhb[src];
    }
    // fused input weights -> tf32 fragment-major d_Wfrag
    for (int idx = tid0; idx < 38 * 150 * 128; idx += stride) {
        int kb = idx / 19200;
        int rem = idx - kb * 19200;
        int np = rem >> 7;
        int li = rem & 127;
        int l = li >> 2, slot = li & 3;
        int atom = np * 2 + (slot >> 1);
        int col = atom * 8 + (l >> 2);
        int k = kb * 8 + (l & 3) + ((slot & 1) << 2);
        float v = 0.f;
        if (k < Ex) {
            int colp = (col < G4) ? col : col - G4;
            const float* W = (col < G4) ? Wihf : Wihb;
            int j = colp >> 2, g = colp & 3;
            v = W[(g * Hx + j) * Ex + k];
        }
        d_Wfrag[idx] = to_tf32(v);
    }
    for (int idx = tid0; idx < G4; idx += stride) {
        int j = idx >> 2, g = idx & 3;
        d_bif[idx] = bf[g * Hx + j];
        d_bib[idx] = bbv[g * Hx + j];
    }
    for (int idx = tid0; idx < KCONV * Cc; idx += stride) {
        int o = idx % Cc, r = idx / Cc;
        int kk = r / Cc, i = r - kk * Cc;
        size_t src = (size_t)o * KCONV + i * 3 + kk;
        d_cw1[idx] = c1w[src];
        d_cw2[idx] = c2w[src];
    }
}

// ---------------- xg GEMM v2: frag-major A staging + frag-major B from L2 ------
// A = emb[cat[m]] [65536x300], B = d_Wfrag; out split to d_xg_f/d_xg_b (+bias).
#define ACH 132
__global__ __launch_bounds__(256, 2)
void xg_gemm(const int* __restrict__ cat, const float* __restrict__ emb) {
    __shared__ float As2[2][16 * ACH];   // [buf][chunk = ks*8 + m_atom][132]

    int tid = threadIdx.x;
    int lane = tid & 31, wid = tid >> 5;
    int wm4 = (wid & 1) * 4;            // m-atom base (4 atoms of 16 rows)
    int wn = (wid >> 1) * 32;
    int m0 = blockIdx.y * 128, n0 = blockIdx.x * 128;
    int npg = (n0 + wn) >> 4;

    // ---- staging indexing: 2 float4 positions per thread (512 total) ----
    size_t abase[2]; int q4[2], cbase[2], lfb[2], slot[2], kbl[2];
#pragma unroll
    for (int q = 0; q < 2; q++) {
        int pos = tid * 2 + q;          // 0..511
        int lrow = pos >> 2;            // 0..127
        q4[q] = pos & 3;                // float4 index within 16-K chunk
        abase[q] = (size_t)cat[m0 + lrow] * Ex;
        kbl[q]  = q4[q] >> 1;           // local slab (0/1)
        slot[q] = ((q4[q] & 1) << 1) + ((lrow >> 3) & 1);
        cbase[q] = kbl[q] * 8 + (lrow >> 4);
        lfb[q] = (lrow & 7) * 4;
    }

    float4 ra[2];
    auto loadA = [&](int k0) {
#pragma unroll
        for (int q = 0; q < 2; q++) {
            int k = k0 + q4[q] * 4;
            ra[q] = (k < Ex) ? *(const float4*)(emb + abase[q] + k)
                             : make_float4(0.f, 0.f, 0.f, 0.f);
        }
    };
    auto storeA = [&](int s, int it) {
#pragma unroll
        for (int q = 0; q < 2; q++) {
            int kbg = it * 2 + kbl[q];
            float* dst = As2[s] + cbase[q] * ACH;
            dst[((lfb[q] + 0 + kbg) & 31) * 4 + slot[q]] = to_tf32(ra[q].x);
            dst[((lfb[q] + 1 + kbg) & 31) * 4 + slot[q]] = to_tf32(ra[q].y);
            dst[((lfb[q] + 2 + kbg) & 31) * 4 + slot[q]] = to_tf32(ra[q].z);
            dst[((lfb[q] + 3 + kbg) & 31) * 4 + slot[q]] = to_tf32(ra[q].w);
        }
    };

    float4 breg[2][2];
    auto loadB = [&](int kbg, float4 bp[2]) {
#pragma unroll
        for (int p = 0; p < 2; p++) {
            int np = npg + p;
            bp[p] = (np < 150)
                ? __ldg((const float4*)(d_Wfrag + ((size_t)kbg * 150 + np) * 128 + lane * 4))
                : make_float4(0.f, 0.f, 0.f, 0.f);
        }
    };

    float acc[4][4][4];
#pragma unroll
    for (int i = 0; i < 4; i++)
#pragma unroll
        for (int j = 0; j < 4; j++)
#pragma unroll
            for (int q = 0; q < 4; q++) acc[i][j][q] = 0.f;

    int r = lane >> 2, c = lane & 3;

    loadA(0); storeA(0, 0);
    loadB(0, breg[0]);
    __syncthreads();

    for (int it = 0; it < 19; it++) {
        if (it + 1 < 19) loadA((it + 1) * 16);
        const float* As = As2[it & 1];
#pragma unroll
        for (int ks = 0; ks < 2; ks++) {
            int kbg = it * 2 + ks;
            if (kbg + 1 < 38) loadB(kbg + 1, breg[(kbg + 1) & 1]);
            int rot = ((lane + kbg) & 31) << 2;
            uint32_t af[4][4];
#pragma unroll
            for (int mt = 0; mt < 4; mt++) {
                float4 a4 = *(const float4*)(As + (ks * 8 + wm4 + mt) * ACH + rot);
                af[mt][0] = __float_as_uint(a4.x);
                af[mt][1] = __float_as_uint(a4.y);
                af[mt][2] = __float_as_uint(a4.z);
                af[mt][3] = __float_as_uint(a4.w);
            }
            float4* bp = breg[kbg & 1];
            uint32_t bf[4][2];
#pragma unroll
            for (int p = 0; p < 2; p++) {
                bf[p * 2 + 0][0] = __float_as_uint(bp[p].x);
                bf[p * 2 + 0][1] = __float_as_uint(bp[p].y);
                bf[p * 2 + 1][0] = __float_as_uint(bp[p].z);
                bf[p * 2 + 1][1] = __float_as_uint(bp[p].w);
            }
#pragma unroll
            for (int mt = 0; mt < 4; mt++)
#pragma unroll
                for (int nt = 0; nt < 4; nt++) {
                    asm volatile(
                        "mma.sync.aligned.m16n8k8.row.col.f32.tf32.tf32.f32 "
                        "{%0,%1,%2,%3}, {%4,%5,%6,%7}, {%8,%9}, {%0,%1,%2,%3};"
                        : "+f"(acc[mt][nt][0]), "+f"(acc[mt][nt][1]),
                          "+f"(acc[mt][nt][2]), "+f"(acc[mt][nt][3])
                        : "r"(af[mt][0]), "r"(af[mt][1]), "r"(af[mt][2]), "r"(af[mt][3]),
                          "r"(bf[nt][0]), "r"(bf[nt][1]));
                }
        }
        if (it + 1 < 19) storeA((it + 1) & 1, it + 1);
        __syncthreads();
    }

    // epilogue: split halves, add bias
#pragma unroll
    for (int mt = 0; mt < 4; mt++) {
#pragma unroll
        for (int j2 = 0; j2 < 2; j2++) {
            int m = m0 + (wm4 + mt) * 16 + r + j2 * 8;
#pragma unroll
            for (int nt = 0; nt < 4; nt++) {
                int n = n0 + wn + (nt >> 1) * 16 + (nt & 1) * 8 + c * 2;
#pragma unroll
                for (int jj = 0; jj < 2; jj++) {
                    int nn = n + jj;
                    float v = acc[mt][nt][j2 * 2 + jj];
                    if (nn < G4)
                        d_xg_f[(size_t)m * G4 + nn] = v + d_bif[nn];
                    else if (nn < 2400)
                        d_xg_b[(size_t)m * G4 + (nn - G4)] = v + d_bib[nn - G4];
                }
            }
        }
    }
}

// ---------------- conv1 GEMM (proven template) ---------------------------------
#define LDSW 136
__global__ __launch_bounds__(256, 2)
void conv_gemm(const float* __restrict__ extbias) {
    constexpr int N = Cc, K = KCONV, BK = 16;
    const float* A = d_ca;
    const float* Bw = d_cw1;
    float* Cout = d_x2row;

    __shared__ float As[2][BK][LDSW];
    __shared__ float Bs[2][BK][LDSW];

    int tid = threadIdx.x;
    int lane = tid & 31, wid = tid >> 5;
    int wm = (wid & 1) * 64;
    int wn = (wid >> 1) * 32;
    int m0 = blockIdx.y * 128, n0 = blockIdx.x * 128;

    size_t abase[2]; int arow[2], akq[2];
    int bkr[2], bnq[2];
#pragma unroll
    for (int q = 0; q < 2; q++) {
        int pos = tid + 256 * q;
        arow[q] = pos >> 2;
        akq[q]  = (pos & 3) * 4;
        abase[q] = (size_t)(m0 + arow[q]) * K;
        bkr[q] = pos >> 5;
        bnq[q] = (pos & 31) * 4;
    }

    float4 ra[2], rb[2];
    auto load_tiles = [&](int k0) {
#pragma unroll
        for (int q = 0; q < 2; q++) {
            int k = k0 + akq[q];
            ra[q] = (k < K) ? *(const float4*)(A + abase[q] + k)
                            : make_float4(0.f, 0.f, 0.f, 0.f);
            int kb = k0 + bkr[q], n = n0 + bnq[q];
            rb[q] = (kb < K && n < N) ? *(const float4*)(Bw + (size_t)kb * N + n)
                                      : make_float4(0.f, 0.f, 0.f, 0.f);
        }
    };
    auto store_tiles = [&](int s) {
#pragma unroll
        for (int q = 0; q < 2; q++) {
            As[s][akq[q] + 0][arow[q]] = to_tf32(ra[q].x);
            As[s][akq[q] + 1][arow[q]] = to_tf32(ra[q].y);
            As[s][akq[q] + 2][arow[q]] = to_tf32(ra[q].z);
            As[s][akq[q] + 3][arow[q]] = to_tf32(ra[q].w);
            Bs[s][bkr[q]][bnq[q] + 0] = to_tf32(rb[q].x);
            Bs[s][bkr[q]][bnq[q] + 1] = to_tf32(rb[q].y);
            Bs[s][bkr[q]][bnq[q] + 2] = to_tf32(rb[q].z);
            Bs[s][bkr[q]][bnq[q] + 3] = to_tf32(rb[q].w);
        }
    };

    float acc[4][4][4];
#pragma unroll
    for (int i = 0; i < 4; i++)
#pragma unroll
        for (int j = 0; j < 4; j++)
#pragma unroll
            for (int q = 0; q < 4; q++) acc[i][j][q] = 0.f;

    int r = lane >> 2, c = lane & 3;

    auto compute = [&](int s) {
#pragma unroll
        for (int ks = 0; ks < 2; ks++) {
            int kb = ks * 8;
            uint32_t af[4][4], bf[4][2];
#pragma unroll
            for (int mt = 0; mt < 4; mt++) {
                int mb = wm + mt * 16 + r;
                af[mt][0] = __float_as_uint(As[s][kb + c][mb]);
                af[mt][1] = __float_as_uint(As[s][kb + c][mb + 8]);
                af[mt][2] = __float_as_uint(As[s][kb + c + 4][mb]);
                af[mt][3] = __float_as_uint(As[s][kb + c + 4][mb + 8]);
            }
#pragma unroll
            for (int nt = 0; nt < 4; nt++) {
                int nb = wn + nt * 8 + r;
                bf[nt][0] = __float_as_uint(Bs[s][kb + c][nb]);
                bf[nt][1] = __float_as_uint(Bs[s][kb + c + 4][nb]);
            }
#pragma unroll
            for (int mt = 0; mt < 4; mt++)
#pragma unroll
                for (int nt = 0; nt < 4; nt++) {
                    asm volatile(
                        "mma.sync.aligned.m16n8k8.row.col.f32.tf32.tf32.f32 "
                        "{%0,%1,%2,%3}, {%4,%5,%6,%7}, {%8,%9}, {%0,%1,%2,%3};"
                        : "+f"(acc[mt][nt][0]), "+f"(acc[mt][nt][1]),
                          "+f"(acc[mt][nt][2]), "+f"(acc[mt][nt][3])
                        : "r"(af[mt][0]), "r"(af[mt][1]), "r"(af[mt][2]), "r"(af[mt][3]),
                          "r"(bf[nt][0]), "r"(bf[nt][1]));
                }
        }
    };

    constexpr int NK = (K + BK - 1) / BK;
    load_tiles(0);
    store_tiles(0);
    __syncthreads();
    for (int it = 0; it < NK; it++) {
        if (it + 1 < NK) load_tiles((it + 1) * BK);
        compute(it & 1);
        if (it + 1 < NK) store_tiles((it + 1) & 1);
        __syncthreads();
    }

#pragma unroll
    for (int mt = 0; mt < 4; mt++) {
#pragma unroll
        for (int j2 = 0; j2 < 2; j2++) {
            int m = m0 + wm + mt * 16 + r + j2 * 8;
            float scl = d_rowscale[m];
#pragma unroll
            for (int nt = 0; nt < 4; nt++) {
                int n = n0 + wn + nt * 8 + c * 2;
#pragma unroll
                for (int jj = 0; jj < 2; jj++) {
                    int nn = n + jj;
                    if (nn < N) {
                        float v = acc[mt][nt][j2 * 2 + jj] + extbias[nn];
                        v = fmaxf(v, 0.f) * scl;
                        Cout[(size_t)m * N + nn] = v;
                    }
                }
            }
        }
    }
}

// ---------------- persistent LSTM v5 (R12 champion config) ---------------------
#define AVCH 132
#define WS3_FLOATS (38 * 6 * AVCH)   // 30096
#define AV3_FLOATS (38 * 4 * AVCH)   // 20064
#define LSTM3_SMEM ((WS3_FLOATS + AV3_FLOATS) * 4)   // 200640

__global__ __launch_bounds__(256, 1)
void lstm_persist5() {
    extern __shared__ float sm[];
    float* Ws = sm;                  // [kb*6+np][132]
    float* Av = sm + WS3_FLOATS;     // [kb*4+mt][132]

    const int tid = threadIdx.x;
    const int lane = tid & 31, wid = tid >> 5;
    const int rt = blockIdx.x / 13, ct = blockIdx.x % 13;
    const int row0 = rt * 64, col0 = ct * 96;
    const bool bwd = (row0 >= 256);
    const float* Wt = bwd ? d_Whhb_t : d_Whhf_t;
    const float* xg = bwd ? d_xg_b : d_xg_f;

    // one-time: W tile -> frag-major smem (tf32)
    for (int idx = tid; idx < 38 * 6 * 128; idx += 256) {
        int kb = idx / (6 * 128);
        int rem = idx - kb * 6 * 128;
        int np = rem >> 7;
        int li = rem & 127;
        int l = li >> 2, slot = li & 3;
        int atom = np * 2 + (slot >> 1);
        int col = col0 + atom * 8 + (l >> 2);
        int k = kb * 8 + (l & 3) + (slot & 1) * 4;
        float v = (k < Hx && col < G4) ? Wt[(size_t)k * G4 + col] : 0.f;
        Ws[(kb * 6 + np) * AVCH + li] = to_tf32(v);
    }
    __syncthreads();

    const int r = lane >> 2, c = lane & 3;
    const int mtw = wid & 3;
    const int nw  = wid >> 2;
    const bool evenc = ((c & 1) == 0);
    const int oddc = evenc ? 0 : 1;
    const int cpair = c >> 1;
    const int row_g = row0 + mtw * 16 + r + (evenc ? 0 : 8);
    const int b = row_g & 255;
    const int Lb = d_L[b];
    unsigned* barp = &d_barg[rt * 32];

    int jidx[6];
#pragma unroll
    for (int a = 0; a < 6; a++)
        jidx[a] = ((col0 + (nw * 6 + a) * 8) >> 2) + cpair;

    float cst[6] = {0.f, 0.f, 0.f, 0.f, 0.f, 0.f};

    for (int t = 0; t < Sx; t++) {
        const float* src = d_hf + ((size_t)((t & 1) * 8 + rt)) * 19456;
        float*       dstg = d_hf + ((size_t)(((t + 1) & 1) * 8 + rt)) * 19456;

        int tsrc = bwd ? ((t < Lb) ? (Lb - 1 - t) : t) : t;
        int pos  = bwd ? tsrc : t;
        const float* xgrow = xg + ((size_t)(b * Sx + tsrc)) * G4;
        float4 xv[6];
#pragma unroll
        for (int a = 0; a < 6; a++)
            xv[a] = (jidx[a] < Hx) ? __ldg((const float4*)(xgrow + jidx[a] * 4))
                                   : make_float4(0.f, 0.f, 0.f, 0.f);

#pragma unroll
        for (int q = 0; q < 19; q++) {
            int f = tid + 256 * q;
            int chunk = f >> 5, off = f & 31;
            float4 v = __ldcg((const float4*)(src + (size_t)f * 4));
            *(float4*)(Av + chunk * AVCH + off * 4) = v;
        }
        __syncthreads();

        float acc[6][4];
#pragma unroll
        for (int a = 0; a < 6; a++)
#pragma unroll
            for (int q = 0; q < 4; q++) acc[a][q] = 0.f;

#pragma unroll 2
        for (int kb = 0; kb < 38; kb++) {
            float4 a4 = *(const float4*)(Av + (kb * 4 + mtw) * AVCH
                                         + (((lane + kb) & 31) << 2));
            uint32_t af0 = __float_as_uint(a4.x), af1 = __float_as_uint(a4.y);
            uint32_t af2 = __float_as_uint(a4.z), af3 = __float_as_uint(a4.w);
#pragma unroll
            for (int p = 0; p < 3; p++) {
                float4 b4 = *(const float4*)(Ws + (kb * 6 + nw * 3 + p) * AVCH
                                             + (lane << 2));
                uint32_t b0 = __float_as_uint(b4.x), b1 = __float_as_uint(b4.y);
                uint32_t b2 = __float_as_uint(b4.z), b3 = __float_as_uint(b4.w);
                asm volatile(
                    "mma.sync.aligned.m16n8k8.row.col.f32.tf32.tf32.f32 "
                    "{%0,%1,%2,%3}, {%4,%5,%6,%7}, {%8,%9}, {%0,%1,%2,%3};"
                    : "+f"(acc[p*2][0]), "+f"(acc[p*2][1]),
                      "+f"(acc[p*2][2]), "+f"(acc[p*2][3])
                    : "r"(af0), "r"(af1), "r"(af2), "r"(af3), "r"(b0), "r"(b1));
                asm volatile(
                    "mma.sync.aligned.m16n8k8.row.col.f32.tf32.tf32.f32 "
                    "{%0,%1,%2,%3}, {%4,%5,%6,%7}, {%8,%9}, {%0,%1,%2,%3};"
                    : "+f"(acc[p*2+1][0]), "+f"(acc[p*2+1][1]),
                      "+f"(acc[p*2+1][2]), "+f"(acc[p*2+1][3])
                    : "r"(af0), "r"(af1), "r"(af2), "r"(af3), "r"(b2), "r"(b3));
            }
        }

        float hvals[6];
#pragma unroll
        for (int a = 0; a < 6; a++) {
            float d0 = acc[a][0], d1 = acc[a][1], d2 = acc[a][2], d3 = acc[a][3];
            float x0 = __shfl_xor_sync(0xFFFFFFFFu, evenc ? d2 : d0, 1);
            float x1 = __shfl_xor_sync(0xFFFFFFFFu, evenc ? d3 : d1, 1);
            float gi = evenc ? d0 : x0;
            float gf = evenc ? d1 : x1;
            float gg = evenc ? x0 : d2;
            float go = evenc ? x1 : d3;
            if (jidx[a] < Hx) {
                gi += xv[a].x; gf += xv[a].y; gg += xv[a].z; go += xv[a].w;
                float si = fsig(gi);
                float sf = fsig(gf);
                float so = fsig(go);
                float cn = sf * cst[a] + si * ftanh(gg);
                cst[a] = cn;
                hvals[a] = so * ftanh(cn);
            } else hvals[a] = 0.f;
        }
        size_t tbase = ((size_t)(b * Sx + pos)) * Cc + (bwd ? Hx : 0);
        float mask = (t < Lb) ? 1.f : 0.f;
        bool last = (t == Sx - 1);
#pragma unroll
        for (int a = 0; a < 6; a++) {
            int j = jidx[a];
            if (j < Hx) {
                d_to[tbase + j] = hvals[a] * mask;
                if (!last) {
                    int kb = j >> 3;
                    int slot = (((j >> 2) & 1) << 1) + oddc;
                    int lp = (r * 4 + (j & 3) + kb) & 31;
                    dstg[(kb * 4 + mtw) * 128 + lp * 4 + slot] = to_tf32(hvals[a]);
                }
            }
        }

        if (!last) {
            __syncthreads();
            if (tid == 0) {
                bar_release_add(barp);
                unsigned target = 13u * (unsigned)(t + 1);
                while (bar_acquire_ld(barp) < target) __nanosleep(16);
            }
            __syncthreads();
        }
    }
}

// ---------------- gather conv1 input windows (2 rows per batch) -----------------
__global__ void k_gatherca() {
    int rr = blockIdx.x;
    int b = rr >> 1, side = rr & 1;
    int le = d_left[b];
    int rt = le + d_asp[b] - 1;
    int p = side ? (rt + 1) : (le - 1);
    bool valid = (p >= 0 && p < Sx);
    if (threadIdx.x == 0)
        d_rowscale[rr] = valid ? d_pw[b * Sx + p] : 0.f;
    for (int k = threadIdx.x; k < KCONV; k += blockDim.x) {
        int dk = k / Cc, i = k - dk * Cc;
        int prow = p - 1 + dk;
        float val = 0.f;
        if (valid && prow >= 0 && prow < Sx)
            val = d_to[((size_t)(b * Sx + prow)) * Cc + i] * d_pw[b * Sx + prow];
        d_ca[(size_t)rr * KCONV + k] = val;
    }
}

// ---------------- conv2 on the two nonzero rows + v ----------------------------
__global__ void k_vrow(const float* __restrict__ c2bias) {
    __shared__ float s0[Cc], s1[Cc];
    int b = blockIdx.x, tid = threadIdx.x;
    int a = d_asp[b];
    for (int i = tid; i < Cc; i += blockDim.x) {
        s0[i] = d_x2row[(size_t)(b * 2 + 0) * Cc + i];
        s1[i] = d_x2row[(size_t)(b * 2 + 1) * Cc + i];
    }
    __syncthreads();
    float acc0[3] = {0.f, 0.f, 0.f}, acc1[3] = {0.f, 0.f, 0.f};
    for (int i = 0; i < Cc; i++) {
        float a0 = s0[i], a1 = s1[i];
        const float* w0 = d_cw2 + (size_t)i * Cc;
        const float* w2 = d_cw2 + (size_t)(1200 + i) * Cc;
#pragma unroll
        for (int q = 0; q < 3; q++) {
            int o = tid + q * 256;
            if (o < Cc) {
                acc0[q] = fmaf(w0[o], a0, acc0[q]);
                acc1[q] = fmaf(w2[o], a1, acc1[q]);
            }
        }
    }
#pragma unroll
    for (int q = 0; q < 3; q++) {
        int o = tid + q * 256;
        if (o < Cc) {
            float bb = c2bias[o];
            float v;
            if (a == 1) {
                v = fmaxf(acc0[q] + acc1[q] + bb, 0.f);
            } else {
                v = fmaxf(acc0[q] + bb, 0.f) + fmaxf(acc1[q] + bb, 0.f)
                  + (float)(a - 2) * fmaxf(bb, 0.f);
            }
            d_v[b * Cc + o] = v;
        }
    }
}

// ---------------- logits -------------------------------------------------------
__global__ void k_logits() {
    int b = blockIdx.x;
    int w = threadIdx.x >> 5, lane = threadIdx.x & 31;
    int t = blockIdx.y * 8 + w;
    const float* vb = d_v + (size_t)b * Cc;
    const float* to = d_to + ((size_t)(b * Sx + t)) * Cc;
    float s = 0.f;
    for (int c = lane; c < Cc; c += 32) s = fmaf(vb[c], to[c], s);
#pragma unroll
    for (int o = 16; o; o >>= 1) s += __shfl_xor_sync(0xFFFFFFFFu, s, o);
    if (lane == 0) d_logits[b * Sx + t] = s;
}

// ---------------- softmax + feat + fc ------------------------------------------
__global__ void k_final(const float* __restrict__ fcw, const float* __restrict__ fcb,
                        float* __restrict__ out) {
    __shared__ float sred[256];
    __shared__ float salpha[256];
    __shared__ float feat[Cc];
    int b = blockIdx.x, t = threadIdx.x;
    float lg = d_logits[b * Sx + t];
    sred[t] = lg;
    __syncthreads();
    for (int o = 128; o; o >>= 1) { if (t < o) sred[t] = fmaxf(sred[t], sred[t + o]); __syncthreads(); }
    float mx = sred[0];
    __syncthreads();
    float e = expf(lg - mx);
    salpha[t] = e;
    sred[t] = e;
    __syncthreads();
    for (int o = 128; o; o >>= 1) { if (t < o) sred[t] += sred[t + o]; __syncthreads(); }
    float Z = sred[0];
    __syncthreads();
    for (int c = t; c < Cc; c += 256) {
        float f = 0.f;
        for (int tt = 0; tt < Sx; tt++)
            f = fmaf(salpha[tt], d_to[((size_t)(b * Sx + tt)) * Cc + c], f);
        feat[c] = f / Z;
    }
    __syncthreads();
    for (int p = 0; p < 3; p++) {
        float part = 0.f;
        for (int c = t; c < Cc; c += 256) part = fmaf(feat[c], fcw[p * Cc + c], part);
        sred[t] = part;
        __syncthreads();
        for (int o = 128; o; o >>= 1) { if (t < o) sred[t] += sred[t + o]; __syncthreads(); }
        if (t == 0) out[b * 3 + p] = sred[0] + fcb[p];
        __syncthreads();
    }
}

// ---------------- launch -------------------------------------------------------
extern "C" void kernel_launch(void* const* d_in, const int* in_sizes, int n_in,
                              void* d_out, int out_size) {
    (void)in_sizes; (void)n_in; (void)out_size;
    const int*   cat   = (const int*)d_in[0];
    const int*   aspi  = (const int*)d_in[1];
    const int*   lefti = (const int*)d_in[2];
    const float* emb   = (const float*)d_in[3];
    const float* Wihf  = (const float*)d_in[4];
    const float* Whhf  = (const float*)d_in[5];
    const float* bf    = (const float*)d_in[6];
    const float* Wihb  = (const float*)d_in[7];
    const float* Whhb  = (const float*)d_in[8];
    const float* bbv   = (const float*)d_in[9];
    const float* c1w   = (const float*)d_in[10];
    const float* c1b   = (const float*)d_in[11];
    const float* c2w   = (const float*)d_in[12];
    const float* c2b   = (const float*)d_in[13];
    const float* fcw   = (const float*)d_in[14];
    const float* fcb   = (const float*)d_in[15];
    float* out = (float*)d_out;

    cudaFuncSetAttribute(lstm_persist5, cudaFuncAttributeMaxDynamicSharedMemorySize,
                         LSTM3_SMEM);

    k_meta<<<Bx, 256>>>(cat, aspi, lefti);
    k_zero<<<512, 256>>>();
    k_prep<<<2048, 256>>>(Wihf, Whhf, bf, Wihb, Whhb, bbv, c1w, c2w);

    dim3 g1(19, 512);   // N=2400, M=65536
    xg_gemm<<<g1, 256>>>(cat, emb);

    lstm_persist5<<<104, 256, LSTM3_SMEM>>>();

    k_gatherca<<<512, 256>>>();
    dim3 g2(5, 4);      // N=600, M=512
    conv_gemm<<<g2, 256>>>(c1b);
    k_vrow<<<Bx, 256>>>(c2b);

    dim3 g3(Bx, 32);
    k_logits<<<g3, 256>>>();
    k_final<<<Bx, 256>>>(fcw, fcb, out);
}

// round 15
// speedup vs baseline: 1.0636x; 1.0419x over previous
#include <cuda_runtime.h>
#include <stdint.h>
#include <math.h>

#define Bx 256
#define Sx 256
#define Ex 300
#define Hx 300
#define G4 1200     // 4*H
#define Cc 600      // 2*H channels
#define Mx 65536    // B*S
#define KCONV 1800  // 3*Cc

// ---------------- scratch (__device__ globals; zero-init at load) -------------
__device__ float d_xg_f[(size_t)Mx * G4];
__device__ float d_xg_b[(size_t)Mx * G4];
__device__ float d_to[(size_t)Mx * Cc];
// frag-major h ping-pong: [buf][group][152 chunks][128]  (152*128 = 19456)
__device__ float d_hf[2 * 8 * 19456];
__device__ float d_Whhf_t[Hx * G4];             // [k][j*4+g]
__device__ float d_Whhb_t[Hx * G4];
// fused input weights, tf32, fragment-major: [38 slabs][150 pairs][128]
__device__ float d_Wfrag[38 * 150 * 128];
__device__ float d_bif[G4];
__device__ float d_bib[G4];
__device__ float d_cw1[KCONV * Cc];
__device__ float d_cw2[KCONV * Cc];
__device__ float d_pw[Mx];
__device__ int   d_L[Bx], d_asp[Bx], d_left[Bx];
__device__ float d_ca[512 * KCONV];
__device__ float d_x2row[512 * Cc];
__device__ float d_rowscale[512];
__device__ float d_v[Bx * Cc];
__device__ float d_logits[Mx];
__device__ unsigned d_barg[8 * 32];             // one counter per 128B line

__device__ __forceinline__ float to_tf32(float x) {
    uint32_t r;
    asm("cvt.rna.tf32.f32 %0, %1;" : "=r"(r) : "f"(x));
    return __uint_as_float(r);
}
__device__ __forceinline__ float fsig(float x) {
    return __fdividef(1.f, 1.f + __expf(-x));
}
__device__ __forceinline__ float ftanh(float x) {
    return __fdividef(2.f, 1.f + __expf(-2.f * x)) - 1.f;
}
__device__ __forceinline__ void bar_release_add(unsigned* p) {
    asm volatile("red.add.release.gpu.u32 [%0], 1;" :: "l"(p) : "memory");
}
__device__ __forceinline__ unsigned bar_acquire_ld(unsigned* p) {
    unsigned v;
    asm volatile("ld.acquire.gpu.u32 %0, [%1];" : "=r"(v) : "l"(p) : "memory");
    return v;
}

// ---------------- meta ---------------------------------------------------------
__global__ void k_meta(const int* __restrict__ cat, const int* __restrict__ aspi,
                       const int* __restrict__ lefti) {
    __shared__ int s[3];
    int b = blockIdx.x, t = threadIdx.x;
    if (t < 3) s[t] = 0;
    __syncthreads();
    if (cat[b * Sx + t] != 0) atomicAdd(&s[0], 1);
    if (t < 16 && aspi[b * 16 + t] != 0) atomicAdd(&s[1], 1);
    if (t < 128 && lefti[b * 128 + t] != 0) atomicAdd(&s[2], 1);
    __syncthreads();
    int L = s[0], A = s[1], Le = s[2];
    if (t == 0) { d_L[b] = L; d_asp[b] = A; d_left[b] = Le; }
    float na = (float)(L - A);
    int right = Le + A - 1;
    float w;
    if (t < Le)           w = 1.0f - (float)(Le - t) / na;
    else if (t <= right)  w = 0.0f;
    else if (t < L)       w = 1.0f - (float)(t - right) / na;
    else                  w = 0.0f;
    d_pw[b * Sx + t] = w;
}

// ---------------- zero h buffers + group barrier counters ----------------------
__global__ void k_zero() {
    int stride = gridDim.x * blockDim.x;
    int tid0 = blockIdx.x * blockDim.x + threadIdx.x;
    for (int i = tid0; i < 2 * 8 * 19456; i += stride) d_hf[i] = 0.f;
    if (tid0 < 8 * 32) d_barg[tid0] = 0u;
}

// ---------------- weight reshapes ----------------------------------------------
__global__ void k_prep(const float* __restrict__ Wihf, const float* __restrict__ Whhf,
                       const float* __restrict__ bf,
                       const float* __restrict__ Wihb, const float* __restrict__ Whhb,
                       const float* __restrict__ bbv,
                       const float* __restrict__ c1w, const float* __restrict__ c2w) {
    int stride = gridDim.x * blockDim.x;
    int tid0 = blockIdx.x * blockDim.x + threadIdx.x;
    for (int idx = tid0; idx < Ex * G4; idx += stride) {
        int k = idx / G4, col = idx - k * G4;
        int j = col >> 2, g = col & 3;
        int src = (g * Hx + j) * Ex + k;   // Ex == Hx
        d_Whhf_t[idx] = Whhf[src];
        d_Whhb_t[idx] = Whhb[src];
    }
    for (int idx = tid0; idx < 38 * 150 * 128; idx += stride) {
        int kb = idx / 19200;
        int rem = idx - kb * 19200;
        int np = rem >> 7;
        int li = rem & 127;
        int l = li >> 2, slot = li & 3;
        int atom = np * 2 + (slot >> 1);
        int col = atom * 8 + (l >> 2);
        int k = kb * 8 + (l & 3) + ((slot & 1) << 2);
        float v = 0.f;
        if (k < Ex) {
            int colp = (col < G4) ? col : col - G4;
            const float* W = (col < G4) ? Wihf : Wihb;
            int j = colp >> 2, g = colp & 3;
            v = W[(g * Hx + j) * Ex + k];
        }
        d_Wfrag[idx] = to_tf32(v);
    }
    for (int idx = tid0; idx < G4; idx += stride) {
        int j = idx >> 2, g = idx & 3;
        d_bif[idx] = bf[g * Hx + j];
        d_bib[idx] = bbv[g * Hx + j];
    }
    for (int idx = tid0; idx < KCONV * Cc; idx += stride) {
        int o = idx % Cc, r = idx / Cc;
        int kk = r / Cc, i = r - kk * Cc;
        size_t src = (size_t)o * KCONV + i * 3 + kk;
        d_cw1[idx] = c1w[src];
        d_cw2[idx] = c2w[src];
    }
}

// ---------------- xg GEMM (R12 version + dead-tile skip) -----------------------
#define LDSW 136
__global__ __launch_bounds__(256, 2)
void xg_gemm(const int* __restrict__ cat, const float* __restrict__ emb) {
    __shared__ float As[2][16][LDSW];

    int m0 = blockIdx.y * 128;
    // dead-tile skip: second half of a batch whose length fits in the first half
    if ((m0 & 255) == 128 && d_L[m0 >> 8] <= 128) return;

    int tid = threadIdx.x;
    int lane = tid & 31, wid = tid >> 5;
    int wm = (wid & 1) * 64;
    int wn = (wid >> 1) * 32;
    int n0 = blockIdx.x * 128;
    int npg = (n0 + wn) >> 4;

    size_t abase[2]; int arow[2], akq[2];
#pragma unroll
    for (int q = 0; q < 2; q++) {
        int pos = tid + 256 * q;
        arow[q] = pos >> 2;
        akq[q]  = (pos & 3) * 4;
        abase[q] = (size_t)cat[m0 + arow[q]] * Ex;
    }

    float4 ra[2];
    auto loadA = [&](int k0) {
#pragma unroll
        for (int q = 0; q < 2; q++) {
            int k = k0 + akq[q];
            ra[q] = (k < Ex) ? *(const float4*)(emb + abase[q] + k)
                             : make_float4(0.f, 0.f, 0.f, 0.f);
        }
    };
    auto storeA = [&](int s) {
#pragma unroll
        for (int q = 0; q < 2; q++) {
            As[s][akq[q] + 0][arow[q]] = to_tf32(ra[q].x);
            As[s][akq[q] + 1][arow[q]] = to_tf32(ra[q].y);
            As[s][akq[q] + 2][arow[q]] = to_tf32(ra[q].z);
            As[s][akq[q] + 3][arow[q]] = to_tf32(ra[q].w);
        }
    };

    float4 breg[2][2];
    auto loadB = [&](int kbg, float4 bp[2]) {
#pragma unroll
        for (int p = 0; p < 2; p++) {
            int np = npg + p;
            bp[p] = (np < 150)
                ? __ldg((const float4*)(d_Wfrag + ((size_t)kbg * 150 + np) * 128 + lane * 4))
                : make_float4(0.f, 0.f, 0.f, 0.f);
        }
    };

    float acc[4][4][4];
#pragma unroll
    for (int i = 0; i < 4; i++)
#pragma unroll
        for (int j = 0; j < 4; j++)
#pragma unroll
            for (int q = 0; q < 4; q++) acc[i][j][q] = 0.f;

    int r = lane >> 2, c = lane & 3;

    loadA(0); storeA(0);
    loadB(0, breg[0]);
    __syncthreads();

    for (int it = 0; it < 19; it++) {
        if (it + 1 < 19) loadA((it + 1) * 16);
#pragma unroll
        for (int ks = 0; ks < 2; ks++) {
            int kbg = it * 2 + ks;
            if (kbg + 1 < 38) loadB(kbg + 1, breg[(kbg + 1) & 1]);
            int kb = ks * 8;
            int s = it & 1;
            uint32_t af[4][4];
#pragma unroll
            for (int mt = 0; mt < 4; mt++) {
                int mb = wm + mt * 16 + r;
                af[mt][0] = __float_as_uint(As[s][kb + c][mb]);
                af[mt][1] = __float_as_uint(As[s][kb + c][mb + 8]);
                af[mt][2] = __float_as_uint(As[s][kb + c + 4][mb]);
                af[mt][3] = __float_as_uint(As[s][kb + c + 4][mb + 8]);
            }
            float4* bp = breg[kbg & 1];
            uint32_t bf[4][2];
#pragma unroll
            for (int p = 0; p < 2; p++) {
                bf[p * 2 + 0][0] = __float_as_uint(bp[p].x);
                bf[p * 2 + 0][1] = __float_as_uint(bp[p].y);
                bf[p * 2 + 1][0] = __float_as_uint(bp[p].z);
                bf[p * 2 + 1][1] = __float_as_uint(bp[p].w);
            }
#pragma unroll
            for (int mt = 0; mt < 4; mt++)
#pragma unroll
                for (int nt = 0; nt < 4; nt++) {
                    asm volatile(
                        "mma.sync.aligned.m16n8k8.row.col.f32.tf32.tf32.f32 "
                        "{%0,%1,%2,%3}, {%4,%5,%6,%7}, {%8,%9}, {%0,%1,%2,%3};"
                        : "+f"(acc[mt][nt][0]), "+f"(acc[mt][nt][1]),
                          "+f"(acc[mt][nt][2]), "+f"(acc[mt][nt][3])
                        : "r"(af[mt][0]), "r"(af[mt][1]), "r"(af[mt][2]), "r"(af[mt][3]),
                          "r"(bf[nt][0]), "r"(bf[nt][1]));
                }
        }
        if (it + 1 < 19) storeA((it + 1) & 1);
        __syncthreads();
    }

#pragma unroll
    for (int mt = 0; mt < 4; mt++) {
#pragma unroll
        for (int j2 = 0; j2 < 2; j2++) {
            int m = m0 + wm + mt * 16 + r + j2 * 8;
#pragma unroll
            for (int nt = 0; nt < 4; nt++) {
                int n = n0 + wn + (nt >> 1) * 16 + (nt & 1) * 8 + c * 2;
#pragma unroll
                for (int jj = 0; jj < 2; jj++) {
                    int nn = n + jj;
                    float v = acc[mt][nt][j2 * 2 + jj];
                    if (nn < G4)
                        d_xg_f[(size_t)m * G4 + nn] = v + d_bif[nn];
                    else if (nn < 2400)
                        d_xg_b[(size_t)m * G4 + (nn - G4)] = v + d_bib[nn - G4];
                }
            }
        }
    }
}

// ---------------- conv1 GEMM (proven template) ---------------------------------
__global__ __launch_bounds__(256, 2)
void conv_gemm(const float* __restrict__ extbias) {
    constexpr int N = Cc, K = KCONV, BK = 16;
    const float* A = d_ca;
    const float* Bw = d_cw1;
    float* Cout = d_x2row;

    __shared__ float As[2][BK][LDSW];
    __shared__ float Bs[2][BK][LDSW];

    int tid = threadIdx.x;
    int lane = tid & 31, wid = tid >> 5;
    int wm = (wid & 1) * 64;
    int wn = (wid >> 1) * 32;
    int m0 = blockIdx.y * 128, n0 = blockIdx.x * 128;

    size_t abase[2]; int arow[2], akq[2];
    int bkr[2], bnq[2];
#pragma unroll
    for (int q = 0; q < 2; q++) {
        int pos = tid + 256 * q;
        arow[q] = pos >> 2;
        akq[q]  = (pos & 3) * 4;
        abase[q] = (size_t)(m0 + arow[q]) * K;
        bkr[q] = pos >> 5;
        bnq[q] = (pos & 31) * 4;
    }

    float4 ra[2], rb[2];
    auto load_tiles = [&](int k0) {
#pragma unroll
        for (int q = 0; q < 2; q++) {
            int k = k0 + akq[q];
            ra[q] = (k < K) ? *(const float4*)(A + abase[q] + k)
                            : make_float4(0.f, 0.f, 0.f, 0.f);
            int kb = k0 + bkr[q], n = n0 + bnq[q];
            rb[q] = (kb < K && n < N) ? *(const float4*)(Bw + (size_t)kb * N + n)
                                      : make_float4(0.f, 0.f, 0.f, 0.f);
        }
    };
    auto store_tiles = [&](int s) {
#pragma unroll
        for (int q = 0; q < 2; q++) {
            As[s][akq[q] + 0][arow[q]] = to_tf32(ra[q].x);
            As[s][akq[q] + 1][arow[q]] = to_tf32(ra[q].y);
            As[s][akq[q] + 2][arow[q]] = to_tf32(ra[q].z);
            As[s][akq[q] + 3][arow[q]] = to_tf32(ra[q].w);
            Bs[s][bkr[q]][bnq[q] + 0] = to_tf32(rb[q].x);
            Bs[s][bkr[q]][bnq[q] + 1] = to_tf32(rb[q].y);
            Bs[s][bkr[q]][bnq[q] + 2] = to_tf32(rb[q].z);
            Bs[s][bkr[q]][bnq[q] + 3] = to_tf32(rb[q].w);
        }
    };

    float acc[4][4][4];
#pragma unroll
    for (int i = 0; i < 4; i++)
#pragma unroll
        for (int j = 0; j < 4; j++)
#pragma unroll
            for (int q = 0; q < 4; q++) acc[i][j][q] = 0.f;

    int r = lane >> 2, c = lane & 3;

    auto compute = [&](int s) {
#pragma unroll
        for (int ks = 0; ks < 2; ks++) {
            int kb = ks * 8;
            uint32_t af[4][4], bf[4][2];
#pragma unroll
            for (int mt = 0; mt < 4; mt++) {
                int mb = wm + mt * 16 + r;
                af[mt][0] = __float_as_uint(As[s][kb + c][mb]);
                af[mt][1] = __float_as_uint(As[s][kb + c][mb + 8]);
                af[mt][2] = __float_as_uint(As[s][kb + c + 4][mb]);
                af[mt][3] = __float_as_uint(As[s][kb + c + 4][mb + 8]);
            }
#pragma unroll
            for (int nt = 0; nt < 4; nt++) {
                int nb = wn + nt * 8 + r;
                bf[nt][0] = __float_as_uint(Bs[s][kb + c][nb]);
                bf[nt][1] = __float_as_uint(Bs[s][kb + c + 4][nb]);
            }
#pragma unroll
            for (int mt = 0; mt < 4; mt++)
#pragma unroll
                for (int nt = 0; nt < 4; nt++) {
                    asm volatile(
                        "mma.sync.aligned.m16n8k8.row.col.f32.tf32.tf32.f32 "
                        "{%0,%1,%2,%3}, {%4,%5,%6,%7}, {%8,%9}, {%0,%1,%2,%3};"
                        : "+f"(acc[mt][nt][0]), "+f"(acc[mt][nt][1]),
                          "+f"(acc[mt][nt][2]), "+f"(acc[mt][nt][3])
                        : "r"(af[mt][0]), "r"(af[mt][1]), "r"(af[mt][2]), "r"(af[mt][3]),
                          "r"(bf[nt][0]), "r"(bf[nt][1]));
                }
        }
    };

    constexpr int NK = (K + BK - 1) / BK;
    load_tiles(0);
    store_tiles(0);
    __syncthreads();
    for (int it = 0; it < NK; it++) {
        if (it + 1 < NK) load_tiles((it + 1) * BK);
        compute(it & 1);
        if (it + 1 < NK) store_tiles((it + 1) & 1);
        __syncthreads();
    }

#pragma unroll
    for (int mt = 0; mt < 4; mt++) {
#pragma unroll
        for (int j2 = 0; j2 < 2; j2++) {
            int m = m0 + wm + mt * 16 + r + j2 * 8;
            float scl = d_rowscale[m];
#pragma unroll
            for (int nt = 0; nt < 4; nt++) {
                int n = n0 + wn + nt * 8 + c * 2;
#pragma unroll
                for (int jj = 0; jj < 2; jj++) {
                    int nn = n + jj;
                    if (nn < N) {
                        float v = acc[mt][nt][j2 * 2 + jj] + extbias[nn];
                        v = fmaxf(v, 0.f) * scl;
                        Cout[(size_t)m * N + nn] = v;
                    }
                }
            }
        }
    }
}

// ---------------- persistent LSTM v7: split staging overlap --------------------
#define AVCH 132
#define WS3_FLOATS (38 * 6 * AVCH)   // 30096
#define AV3_FLOATS (38 * 4 * AVCH)   // 20064
#define LSTM3_SMEM ((WS3_FLOATS + AV3_FLOATS) * 4)   // 200640

__global__ __launch_bounds__(256, 1)
void lstm_persist7() {
    extern __shared__ float sm[];
    float* Ws = sm;                  // [kb*6+np][132]
    float* Av = sm + WS3_FLOATS;     // [kb*4+mt][132]

    const int tid = threadIdx.x;
    const int lane = tid & 31, wid = tid >> 5;
    const int rt = blockIdx.x / 13, ct = blockIdx.x % 13;
    const int row0 = rt * 64, col0 = ct * 96;
    const bool bwd = (row0 >= 256);
    const float* Wt = bwd ? d_Whhb_t : d_Whhf_t;
    const float* xg = bwd ? d_xg_b : d_xg_f;

    for (int idx = tid; idx < 38 * 6 * 128; idx += 256) {
        int kb = idx / (6 * 128);
        int rem = idx - kb * 6 * 128;
        int np = rem >> 7;
        int li = rem & 127;
        int l = li >> 2, slot = li & 3;
        int atom = np * 2 + (slot >> 1);
        int col = col0 + atom * 8 + (l >> 2);
        int k = kb * 8 + (l & 3) + (slot & 1) * 4;
        float v = (k < Hx && col < G4) ? Wt[(size_t)k * G4 + col] : 0.f;
        Ws[(kb * 6 + np) * AVCH + li] = to_tf32(v);
    }
    __syncthreads();

    const int r = lane >> 2, c = lane & 3;
    const int mtw = wid & 3;
    const int nw  = wid >> 2;
    const bool evenc = ((c & 1) == 0);
    const int oddc = evenc ? 0 : 1;
    const int cpair = c >> 1;
    const int row_g = row0 + mtw * 16 + r + (evenc ? 0 : 8);
    const int b = row_g & 255;
    const int Lb = d_L[b];
    unsigned* barp = &d_barg[rt * 32];

    int jidx[6];
#pragma unroll
    for (int a = 0; a < 6; a++)
        jidx[a] = ((col0 + (nw * 6 + a) * 8) >> 2) + cpair;

    float cst[6] = {0.f, 0.f, 0.f, 0.f, 0.f, 0.f};

    // MMA over a kb range
    auto mma_range = [&](float acc[6][4], int kb0, int kb1) {
#pragma unroll 2
        for (int kb = kb0; kb < kb1; kb++) {
            float4 a4 = *(const float4*)(Av + (kb * 4 + mtw) * AVCH
                                         + (((lane + kb) & 31) << 2));
            uint32_t af0 = __float_as_uint(a4.x), af1 = __float_as_uint(a4.y);
            uint32_t af2 = __float_as_uint(a4.z), af3 = __float_as_uint(a4.w);
#pragma unroll
            for (int p = 0; p < 3; p++) {
                float4 b4 = *(const float4*)(Ws + (kb * 6 + nw * 3 + p) * AVCH
                                             + (lane << 2));
                uint32_t b0 = __float_as_uint(b4.x), b1 = __float_as_uint(b4.y);
                uint32_t b2 = __float_as_uint(b4.z), b3 = __float_as_uint(b4.w);
                asm volatile(
                    "mma.sync.aligned.m16n8k8.row.col.f32.tf32.tf32.f32 "
                    "{%0,%1,%2,%3}, {%4,%5,%6,%7}, {%8,%9}, {%0,%1,%2,%3};"
                    : "+f"(acc[p*2][0]), "+f"(acc[p*2][1]),
                      "+f"(acc[p*2][2]), "+f"(acc[p*2][3])
                    : "r"(af0), "r"(af1), "r"(af2), "r"(af3), "r"(b0), "r"(b1));
                asm volatile(
                    "mma.sync.aligned.m16n8k8.row.col.f32.tf32.tf32.f32 "
                    "{%0,%1,%2,%3}, {%4,%5,%6,%7}, {%8,%9}, {%0,%1,%2,%3};"
                    : "+f"(acc[p*2+1][0]), "+f"(acc[p*2+1][1]),
                      "+f"(acc[p*2+1][2]), "+f"(acc[p*2+1][3])
                    : "r"(af0), "r"(af1), "r"(af2), "r"(af3), "r"(b2), "r"(b3));
            }
        }
    };

    for (int t = 0; t < Sx; t++) {
        const float* src = d_hf + ((size_t)((t & 1) * 8 + rt)) * 19456;
        float*       dstg = d_hf + ((size_t)(((t + 1) & 1) * 8 + rt)) * 19456;

        int tsrc = bwd ? ((t < Lb) ? (Lb - 1 - t) : t) : t;
        int pos  = bwd ? tsrc : t;
        const float* xgrow = xg + ((size_t)(b * Sx + tsrc)) * G4;
        float4 xv[6];
#pragma unroll
        for (int a = 0; a < 6; a++)
            xv[a] = (jidx[a] < Hx) ? __ldg((const float4*)(xgrow + jidx[a] * 4))
                                   : make_float4(0.f, 0.f, 0.f, 0.f);

        // ---- stage part 1 (chunks 0..75 = kb 0..18) ----
        float4 h1[10];
#pragma unroll
        for (int q = 0; q < 10; q++) {
            int f = tid + 256 * q;
            h1[q] = (f < 2432) ? __ldcg((const float4*)(src + (size_t)f * 4))
                               : make_float4(0.f, 0.f, 0.f, 0.f);
        }
#pragma unroll
        for (int q = 0; q < 10; q++) {
            int f = tid + 256 * q;
            if (f < 2432) {
                int chunk = f >> 5, off = f & 31;
                *(float4*)(Av + chunk * AVCH + off * 4) = h1[q];
            }
        }
        // ---- issue part 2 loads (overlap with first MMA half) ----
        float4 h2[10];
#pragma unroll
        for (int q = 0; q < 10; q++) {
            int f = 2432 + tid + 256 * q;
            h2[q] = (f < 4864) ? __ldcg((const float4*)(src + (size_t)f * 4))
                               : make_float4(0.f, 0.f, 0.f, 0.f);
        }
        __syncthreads();

        float acc[6][4];
#pragma unroll
        for (int a = 0; a < 6; a++)
#pragma unroll
            for (int q = 0; q < 4; q++) acc[a][q] = 0.f;

        mma_range(acc, 0, 19);

#pragma unroll
        for (int q = 0; q < 10; q++) {
            int f = 2432 + tid + 256 * q;
            if (f < 4864) {
                int chunk = f >> 5, off = f & 31;
                *(float4*)(Av + chunk * AVCH + off * 4) = h2[q];
            }
        }
        __syncthreads();

        mma_range(acc, 19, 38);

        // ---- epilogue ----
        float hvals[6];
#pragma unroll
        for (int a = 0; a < 6; a++) {
            float d0 = acc[a][0], d1 = acc[a][1], d2 = acc[a][2], d3 = acc[a][3];
            float x0 = __shfl_xor_sync(0xFFFFFFFFu, evenc ? d2 : d0, 1);
            float x1 = __shfl_xor_sync(0xFFFFFFFFu, evenc ? d3 : d1, 1);
            float gi = evenc ? d0 : x0;
            float gf = evenc ? d1 : x1;
            float gg = evenc ? x0 : d2;
            float go = evenc ? x1 : d3;
            if (jidx[a] < Hx) {
                gi += xv[a].x; gf += xv[a].y; gg += xv[a].z; go += xv[a].w;
                float si = fsig(gi);
                float sf = fsig(gf);
                float so = fsig(go);
                float cn = sf * cst[a] + si * ftanh(gg);
                cst[a] = cn;
                hvals[a] = so * ftanh(cn);
            } else hvals[a] = 0.f;
        }
        size_t tbase = ((size_t)(b * Sx + pos)) * Cc + (bwd ? Hx : 0);
        float mask = (t < Lb) ? 1.f : 0.f;
        bool last = (t == Sx - 1);
#pragma unroll
        for (int a = 0; a < 6; a++) {
            int j = jidx[a];
            if (j < Hx) {
                d_to[tbase + j] = hvals[a] * mask;
                if (!last) {
                    int kb = j >> 3;
                    int slot = (((j >> 2) & 1) << 1) + oddc;
                    int lp = (r * 4 + (j & 3) + kb) & 31;
                    dstg[(kb * 4 + mtw) * 128 + lp * 4 + slot] = to_tf32(hvals[a]);
                }
            }
        }

        if (!last) {
            __syncthreads();
            if (tid == 0) {
                bar_release_add(barp);
                unsigned target = 13u * (unsigned)(t + 1);
                while (bar_acquire_ld(barp) < target) __nanosleep(16);
            }
            __syncthreads();
        }
    }
}

// ---------------- gather conv1 input windows (2 rows per batch) -----------------
__global__ void k_gatherca() {
    int rr = blockIdx.x;
    int b = rr >> 1, side = rr & 1;
    int le = d_left[b];
    int rt = le + d_asp[b] - 1;
    int p = side ? (rt + 1) : (le - 1);
    bool valid = (p >= 0 && p < Sx);
    if (threadIdx.x == 0)
        d_rowscale[rr] = valid ? d_pw[b * Sx + p] : 0.f;
    for (int k = threadIdx.x; k < KCONV; k += blockDim.x) {
        int dk = k / Cc, i = k - dk * Cc;
        int prow = p - 1 + dk;
        float val = 0.f;
        if (valid && prow >= 0 && prow < Sx)
            val = d_to[((size_t)(b * Sx + prow)) * Cc + i] * d_pw[b * Sx + prow];
        d_ca[(size_t)rr * KCONV + k] = val;
    }
}

// ---------------- conv2 on the two nonzero rows + v ----------------------------
__global__ void k_vrow(const float* __restrict__ c2bias) {
    __shared__ float s0[Cc], s1[Cc];
    int b = blockIdx.x, tid = threadIdx.x;
    int a = d_asp[b];
    for (int i = tid; i < Cc; i += blockDim.x) {
        s0[i] = d_x2row[(size_t)(b * 2 + 0) * Cc + i];
        s1[i] = d_x2row[(size_t)(b * 2 + 1) * Cc + i];
    }
    __syncthreads();
    float acc0[3] = {0.f, 0.f, 0.f}, acc1[3] = {0.f, 0.f, 0.f};
    for (int i = 0; i < Cc; i++) {
        float a0 = s0[i], a1 = s1[i];
        const float* w0 = d_cw2 + (size_t)i * Cc;
        const float* w2 = d_cw2 + (size_t)(1200 + i) * Cc;
#pragma unroll
        for (int q = 0; q < 3; q++) {
            int o = tid + q * 256;
            if (o < Cc) {
                acc0[q] = fmaf(w0[o], a0, acc0[q]);
                acc1[q] = fmaf(w2[o], a1, acc1[q]);
            }
        }
    }
#pragma unroll
    for (int q = 0; q < 3; q++) {
        int o = tid + q * 256;
        if (o < Cc) {
            float bb = c2bias[o];
            float v;
            if (a == 1) {
                v = fmaxf(acc0[q] + acc1[q] + bb, 0.f);
            } else {
                v = fmaxf(acc0[q] + bb, 0.f) + fmaxf(acc1[q] + bb, 0.f)
                  + (float)(a - 2) * fmaxf(bb, 0.f);
            }
            d_v[b * Cc + o] = v;
        }
    }
}

// ---------------- logits -------------------------------------------------------
__global__ void k_logits() {
    int b = blockIdx.x;
    int w = threadIdx.x >> 5, lane = threadIdx.x & 31;
    int t = blockIdx.y * 8 + w;
    const float* vb = d_v + (size_t)b * Cc;
    const float* to = d_to + ((size_t)(b * Sx + t)) * Cc;
    float s = 0.f;
    for (int c = lane; c < Cc; c += 32) s = fmaf(vb[c], to[c], s);
#pragma unroll
    for (int o = 16; o; o >>= 1) s += __shfl_xor_sync(0xFFFFFFFFu, s, o);
    if (lane == 0) d_logits[b * Sx + t] = s;
}

// ---------------- softmax + feat + fc ------------------------------------------
__global__ void k_final(const float* __restrict__ fcw, const float* __restrict__ fcb,
                        float* __restrict__ out) {
    __shared__ float sred[256];
    __shared__ float salpha[256];
    __shared__ float feat[Cc];
    int b = blockIdx.x, t = threadIdx.x;
    float lg = d_logits[b * Sx + t];
    sred[t] = lg;
    __syncthreads();
    for (int o = 128; o; o >>= 1) { if (t < o) sred[t] = fmaxf(sred[t], sred[t + o]); __syncthreads(); }
    float mx = sred[0];
    __syncthreads();
    float e = expf(lg - mx);
    salpha[t] = e;
    sred[t] = e;
    __syncthreads();
    for (int o = 128; o; o >>= 1) { if (t < o) sred[t] += sred[t + o]; __syncthreads(); }
    float Z = sred[0];
    __syncthreads();
    for (int c = t; c < Cc; c += 256) {
        float f = 0.f;
        for (int tt = 0; tt < Sx; tt++)
            f = fmaf(salpha[tt], d_to[((size_t)(b * Sx + tt)) * Cc + c], f);
        feat[c] = f / Z;
    }
    __syncthreads();
    for (int p = 0; p < 3; p++) {
        float part = 0.f;
        for (int c = t; c < Cc; c += 256) part = fmaf(feat[c], fcw[p * Cc + c], part);
        sred[t] = part;
        __syncthreads();
        for (int o = 128; o; o >>= 1) { if (t < o) sred[t] += sred[t + o]; __syncthreads(); }
        if (t == 0) out[b * 3 + p] = sred[0] + fcb[p];
        __syncthreads();
    }
}

// ---------------- launch -------------------------------------------------------
extern "C" void kernel_launch(void* const* d_in, const int* in_sizes, int n_in,
                              void* d_out, int out_size) {
    (void)in_sizes; (void)n_in; (void)out_size;
    const int*   cat   = (const int*)d_in[0];
    const int*   aspi  = (const int*)d_in[1];
    const int*   lefti = (const int*)d_in[2];
    const float* emb   = (const float*)d_in[3];
    const float* Wihf  = (const float*)d_in[4];
    const float* Whhf  = (const float*)d_in[5];
    const float* bf    = (const float*)d_in[6];
    const float* Wihb  = (const float*)d_in[7];
    const float* Whhb  = (const float*)d_in[8];
    const float* bbv   = (const float*)d_in[9];
    const float* c1w   = (const float*)d_in[10];
    const float* c1b   = (const float*)d_in[11];
    const float* c2w   = (const float*)d_in[12];
    const float* c2b   = (const float*)d_in[13];
    const float* fcw   = (const float*)d_in[14];
    const float* fcb   = (const float*)d_in[15];
    float* out = (float*)d_out;

    cudaFuncSetAttribute(lstm_persist7, cudaFuncAttributeMaxDynamicSharedMemorySize,
                         LSTM3_SMEM);

    k_meta<<<Bx, 256>>>(cat, aspi, lefti);
    k_zero<<<512, 256>>>();
    k_prep<<<2048, 256>>>(Wihf, Whhf, bf, Wihb, Whhb, bbv, c1w, c2w);

    dim3 g1(19, 512);   // N=2400, M=65536
    xg_gemm<<<g1, 256>>>(cat, emb);

    lstm_persist7<<<104, 256, LSTM3_SMEM>>>();

    k_gatherca<<<512, 256>>>();
    dim3 g2(5, 4);      // N=600, M=512
    conv_gemm<<<g2, 256>>>(c1b);
    k_vrow<<<Bx, 256>>>(c2b);

    dim3 g3(Bx, 32);
    k_logits<<<g3, 256>>>();
    k_final<<<Bx, 256>>>(fcw, fcb, out);
}

// round 16
// speedup vs baseline: 1.0908x; 1.0257x over previous
#include <cuda_runtime.h>
#include <stdint.h>
#include <math.h>

#define Bx 256
#define Sx 256
#define Ex 300
#define Hx 300
#define G4 1200     // 4*H
#define Cc 600      // 2*H channels
#define Mx 65536    // B*S
#define KCONV 1800  // 3*Cc

// ---------------- scratch (__device__ globals; zero-init at load) -------------
__device__ float d_xg_f[(size_t)Mx * G4];
__device__ float d_xg_b[(size_t)Mx * G4];
__device__ float d_to[(size_t)Mx * Cc];
// frag-major h ping-pong: [buf][group][152 chunks][128]  (152*128 = 19456)
__device__ float d_hf[2 * 8 * 19456];
__device__ float d_Whhf_t[Hx * G4];             // [k][j*4+g]
__device__ float d_Whhb_t[Hx * G4];
// fused input weights, tf32, fragment-major: [38 slabs][150 pairs][128]
__device__ float d_Wfrag[38 * 150 * 128];
__device__ float d_bif[G4];
__device__ float d_bib[G4];
__device__ float d_cw1[KCONV * Cc];
__device__ float d_cw2[KCONV * Cc];
__device__ float d_pw[Mx];
__device__ int   d_L[Bx], d_asp[Bx], d_left[Bx];
__device__ int   d_Lmax[4];                     // max L per 64-batch group
__device__ float d_ca[512 * KCONV];
__device__ float d_x2row[512 * Cc];
__device__ float d_rowscale[512];
__device__ float d_v[Bx * Cc];
__device__ float d_logits[Mx];
__device__ unsigned d_barg[8 * 32];             // one counter per 128B line

__device__ __forceinline__ float to_tf32(float x) {
    uint32_t r;
    asm("cvt.rna.tf32.f32 %0, %1;" : "=r"(r) : "f"(x));
    return __uint_as_float(r);
}
__device__ __forceinline__ float fsig(float x) {
    return __fdividef(1.f, 1.f + __expf(-x));
}
__device__ __forceinline__ float ftanh(float x) {
    return __fdividef(2.f, 1.f + __expf(-2.f * x)) - 1.f;
}
__device__ __forceinline__ void bar_release_add(unsigned* p) {
    asm volatile("red.add.release.gpu.u32 [%0], 1;" :: "l"(p) : "memory");
}
__device__ __forceinline__ unsigned bar_acquire_ld(unsigned* p) {
    unsigned v;
    asm volatile("ld.acquire.gpu.u32 %0, [%1];" : "=r"(v) : "l"(p) : "memory");
    return v;
}

// ---------------- meta ---------------------------------------------------------
__global__ void k_meta(const int* __restrict__ cat, const int* __restrict__ aspi,
                       const int* __restrict__ lefti) {
    __shared__ int s[3];
    int b = blockIdx.x, t = threadIdx.x;
    if (t < 3) s[t] = 0;
    __syncthreads();
    if (cat[b * Sx + t] != 0) atomicAdd(&s[0], 1);
    if (t < 16 && aspi[b * 16 + t] != 0) atomicAdd(&s[1], 1);
    if (t < 128 && lefti[b * 128 + t] != 0) atomicAdd(&s[2], 1);
    __syncthreads();
    int L = s[0], A = s[1], Le = s[2];
    if (t == 0) {
        d_L[b] = L; d_asp[b] = A; d_left[b] = Le;
        atomicMax(&d_Lmax[b >> 6], L);
    }
    float na = (float)(L - A);
    int right = Le + A - 1;
    float w;
    if (t < Le)           w = 1.0f - (float)(Le - t) / na;
    else if (t <= right)  w = 0.0f;
    else if (t < L)       w = 1.0f - (float)(t - right) / na;
    else                  w = 0.0f;
    d_pw[b * Sx + t] = w;
}

// ---------------- zero h buffer 0 + group barrier counters ---------------------
// buf1 is written (step 0) before first read (step 1); pad chunks multiply
// against zeroed Ws columns, so only buf0 needs per-launch zeroing.
__global__ void k_zero() {
    int stride = gridDim.x * blockDim.x;
    int tid0 = blockIdx.x * blockDim.x + threadIdx.x;
    for (int i = tid0; i < 8 * 19456; i += stride) d_hf[i] = 0.f;
    if (tid0 < 8 * 32) d_barg[tid0] = 0u;
}

// ---------------- weight reshapes ----------------------------------------------
__global__ void k_prep(const float* __restrict__ Wihf, const float* __restrict__ Whhf,
                       const float* __restrict__ bf,
                       const float* __restrict__ Wihb, const float* __restrict__ Whhb,
                       const float* __restrict__ bbv,
                       const float* __restrict__ c1w, const float* __restrict__ c2w) {
    int stride = gridDim.x * blockDim.x;
    int tid0 = blockIdx.x * blockDim.x + threadIdx.x;
    for (int idx = tid0; idx < Ex * G4; idx += stride) {
        int k = idx / G4, col = idx - k * G4;
        int j = col >> 2, g = col & 3;
        int src = (g * Hx + j) * Ex + k;   // Ex == Hx
        d_Whhf_t[idx] = Whhf[src];
        d_Whhb_t[idx] = Whhb[src];
    }
    for (int idx = tid0; idx < 38 * 150 * 128; idx += stride) {
        int kb = idx / 19200;
        int rem = idx - kb * 19200;
        int np = rem >> 7;
        int li = rem & 127;
        int l = li >> 2, slot = li & 3;
        int atom = np * 2 + (slot >> 1);
        int col = atom * 8 + (l >> 2);
        int k = kb * 8 + (l & 3) + ((slot & 1) << 2);
        float v = 0.f;
        if (k < Ex) {
            int colp = (col < G4) ? col : col - G4;
            const float* W = (col < G4) ? Wihf : Wihb;
            int j = colp >> 2, g = colp & 3;
            v = W[(g * Hx + j) * Ex + k];
        }
        d_Wfrag[idx] = to_tf32(v);
    }
    for (int idx = tid0; idx < G4; idx += stride) {
        int j = idx >> 2, g = idx & 3;
        d_bif[idx] = bf[g * Hx + j];
        d_bib[idx] = bbv[g * Hx + j];
    }
    for (int idx = tid0; idx < KCONV * Cc; idx += stride) {
        int o = idx % Cc, r = idx / Cc;
        int kk = r / Cc, i = r - kk * Cc;
        size_t src = (size_t)o * KCONV + i * 3 + kk;
        d_cw1[idx] = c1w[src];
        d_cw2[idx] = c2w[src];
    }
}

// ---------------- xg GEMM (R12 version + dead-tile skip) -----------------------
#define LDSW 136
__global__ __launch_bounds__(256, 2)
void xg_gemm(const int* __restrict__ cat, const float* __restrict__ emb) {
    __shared__ float As[2][16][LDSW];

    int m0 = blockIdx.y * 128;
    if ((m0 & 255) == 128 && d_L[m0 >> 8] <= 128) return;

    int tid = threadIdx.x;
    int lane = tid & 31, wid = tid >> 5;
    int wm = (wid & 1) * 64;
    int wn = (wid >> 1) * 32;
    int n0 = blockIdx.x * 128;
    int npg = (n0 + wn) >> 4;

    size_t abase[2]; int arow[2], akq[2];
#pragma unroll
    for (int q = 0; q < 2; q++) {
        int pos = tid + 256 * q;
        arow[q] = pos >> 2;
        akq[q]  = (pos & 3) * 4;
        abase[q] = (size_t)cat[m0 + arow[q]] * Ex;
    }

    float4 ra[2];
    auto loadA = [&](int k0) {
#pragma unroll
        for (int q = 0; q < 2; q++) {
            int k = k0 + akq[q];
            ra[q] = (k < Ex) ? *(const float4*)(emb + abase[q] + k)
                             : make_float4(0.f, 0.f, 0.f, 0.f);
        }
    };
    auto storeA = [&](int s) {
#pragma unroll
        for (int q = 0; q < 2; q++) {
            As[s][akq[q] + 0][arow[q]] = to_tf32(ra[q].x);
            As[s][akq[q] + 1][arow[q]] = to_tf32(ra[q].y);
            As[s][akq[q] + 2][arow[q]] = to_tf32(ra[q].z);
            As[s][akq[q] + 3][arow[q]] = to_tf32(ra[q].w);
        }
    };

    float4 breg[2][2];
    auto loadB = [&](int kbg, float4 bp[2]) {
#pragma unroll
        for (int p = 0; p < 2; p++) {
            int np = npg + p;
            bp[p] = (np < 150)
                ? __ldg((const float4*)(d_Wfrag + ((size_t)kbg * 150 + np) * 128 + lane * 4))
                : make_float4(0.f, 0.f, 0.f, 0.f);
        }
    };

    float acc[4][4][4];
#pragma unroll
    for (int i = 0; i < 4; i++)
#pragma unroll
        for (int j = 0; j < 4; j++)
#pragma unroll
            for (int q = 0; q < 4; q++) acc[i][j][q] = 0.f;

    int r = lane >> 2, c = lane & 3;

    loadA(0); storeA(0);
    loadB(0, breg[0]);
    __syncthreads();

    for (int it = 0; it < 19; it++) {
        if (it + 1 < 19) loadA((it + 1) * 16);
#pragma unroll
        for (int ks = 0; ks < 2; ks++) {
            int kbg = it * 2 + ks;
            if (kbg + 1 < 38) loadB(kbg + 1, breg[(kbg + 1) & 1]);
            int kb = ks * 8;
            int s = it & 1;
            uint32_t af[4][4];
#pragma unroll
            for (int mt = 0; mt < 4; mt++) {
                int mb = wm + mt * 16 + r;
                af[mt][0] = __float_as_uint(As[s][kb + c][mb]);
                af[mt][1] = __float_as_uint(As[s][kb + c][mb + 8]);
                af[mt][2] = __float_as_uint(As[s][kb + c + 4][mb]);
                af[mt][3] = __float_as_uint(As[s][kb + c + 4][mb + 8]);
            }
            float4* bp = breg[kbg & 1];
            uint32_t bf[4][2];
#pragma unroll
            for (int p = 0; p < 2; p++) {
                bf[p * 2 + 0][0] = __float_as_uint(bp[p].x);
                bf[p * 2 + 0][1] = __float_as_uint(bp[p].y);
                bf[p * 2 + 1][0] = __float_as_uint(bp[p].z);
                bf[p * 2 + 1][1] = __float_as_uint(bp[p].w);
            }
#pragma unroll
            for (int mt = 0; mt < 4; mt++)
#pragma unroll
                for (int nt = 0; nt < 4; nt++) {
                    asm volatile(
                        "mma.sync.aligned.m16n8k8.row.col.f32.tf32.tf32.f32 "
                        "{%0,%1,%2,%3}, {%4,%5,%6,%7}, {%8,%9}, {%0,%1,%2,%3};"
                        : "+f"(acc[mt][nt][0]), "+f"(acc[mt][nt][1]),
                          "+f"(acc[mt][nt][2]), "+f"(acc[mt][nt][3])
                        : "r"(af[mt][0]), "r"(af[mt][1]), "r"(af[mt][2]), "r"(af[mt][3]),
                          "r"(bf[nt][0]), "r"(bf[nt][1]));
                }
        }
        if (it + 1 < 19) storeA((it + 1) & 1);
        __syncthreads();
    }

#pragma unroll
    for (int mt = 0; mt < 4; mt++) {
#pragma unroll
        for (int j2 = 0; j2 < 2; j2++) {
            int m = m0 + wm + mt * 16 + r + j2 * 8;
#pragma unroll
            for (int nt = 0; nt < 4; nt++) {
                int n = n0 + wn + (nt >> 1) * 16 + (nt & 1) * 8 + c * 2;
#pragma unroll
                for (int jj = 0; jj < 2; jj++) {
                    int nn = n + jj;
                    float v = acc[mt][nt][j2 * 2 + jj];
                    if (nn < G4)
                        d_xg_f[(size_t)m * G4 + nn] = v + d_bif[nn];
                    else if (nn < 2400)
                        d_xg_b[(size_t)m * G4 + (nn - G4)] = v + d_bib[nn - G4];
                }
            }
        }
    }
}

// ---------------- conv1 GEMM (proven template) ---------------------------------
__global__ __launch_bounds__(256, 2)
void conv_gemm(const float* __restrict__ extbias) {
    constexpr int N = Cc, K = KCONV, BK = 16;
    const float* A = d_ca;
    const float* Bw = d_cw1;
    float* Cout = d_x2row;

    __shared__ float As[2][BK][LDSW];
    __shared__ float Bs[2][BK][LDSW];

    int tid = threadIdx.x;
    int lane = tid & 31, wid = tid >> 5;
    int wm = (wid & 1) * 64;
    int wn = (wid >> 1) * 32;
    int m0 = blockIdx.y * 128, n0 = blockIdx.x * 128;

    size_t abase[2]; int arow[2], akq[2];
    int bkr[2], bnq[2];
#pragma unroll
    for (int q = 0; q < 2; q++) {
        int pos = tid + 256 * q;
        arow[q] = pos >> 2;
        akq[q]  = (pos & 3) * 4;
        abase[q] = (size_t)(m0 + arow[q]) * K;
        bkr[q] = pos >> 5;
        bnq[q] = (pos & 31) * 4;
    }

    float4 ra[2], rb[2];
    auto load_tiles = [&](int k0) {
#pragma unroll
        for (int q = 0; q < 2; q++) {
            int k = k0 + akq[q];
            ra[q] = (k < K) ? *(const float4*)(A + abase[q] + k)
                            : make_float4(0.f, 0.f, 0.f, 0.f);
            int kb = k0 + bkr[q], n = n0 + bnq[q];
            rb[q] = (kb < K && n < N) ? *(const float4*)(Bw + (size_t)kb * N + n)
                                      : make_float4(0.f, 0.f, 0.f, 0.f);
        }
    };
    auto store_tiles = [&](int s) {
#pragma unroll
        for (int q = 0; q < 2; q++) {
            As[s][akq[q] + 0][arow[q]] = to_tf32(ra[q].x);
            As[s][akq[q] + 1][arow[q]] = to_tf32(ra[q].y);
            As[s][akq[q] + 2][arow[q]] = to_tf32(ra[q].z);
            As[s][akq[q] + 3][arow[q]] = to_tf32(ra[q].w);
            Bs[s][bkr[q]][bnq[q] + 0] = to_tf32(rb[q].x);
            Bs[s][bkr[q]][bnq[q] + 1] = to_tf32(rb[q].y);
            Bs[s][bkr[q]][bnq[q] + 2] = to_tf32(rb[q].z);
            Bs[s][bkr[q]][bnq[q] + 3] = to_tf32(rb[q].w);
        }
    };

    float acc[4][4][4];
#pragma unroll
    for (int i = 0; i < 4; i++)
#pragma unroll
        for (int j = 0; j < 4; j++)
#pragma unroll
            for (int q = 0; q < 4; q++) acc[i][j][q] = 0.f;

    int r = lane >> 2, c = lane & 3;

    auto compute = [&](int s) {
#pragma unroll
        for (int ks = 0; ks < 2; ks++) {
            int kb = ks * 8;
            uint32_t af[4][4], bf[4][2];
#pragma unroll
            for (int mt = 0; mt < 4; mt++) {
                int mb = wm + mt * 16 + r;
                af[mt][0] = __float_as_uint(As[s][kb + c][mb]);
                af[mt][1] = __float_as_uint(As[s][kb + c][mb + 8]);
                af[mt][2] = __float_as_uint(As[s][kb + c + 4][mb]);
                af[mt][3] = __float_as_uint(As[s][kb + c + 4][mb + 8]);
            }
#pragma unroll
            for (int nt = 0; nt < 4; nt++) {
                int nb = wn + nt * 8 + r;
                bf[nt][0] = __float_as_uint(Bs[s][kb + c][nb]);
                bf[nt][1] = __float_as_uint(Bs[s][kb + c + 4][nb]);
            }
#pragma unroll
            for (int mt = 0; mt < 4; mt++)
#pragma unroll
                for (int nt = 0; nt < 4; nt++) {
                    asm volatile(
                        "mma.sync.aligned.m16n8k8.row.col.f32.tf32.tf32.f32 "
                        "{%0,%1,%2,%3}, {%4,%5,%6,%7}, {%8,%9}, {%0,%1,%2,%3};"
                        : "+f"(acc[mt][nt][0]), "+f"(acc[mt][nt][1]),
                          "+f"(acc[mt][nt][2]), "+f"(acc[mt][nt][3])
                        : "r"(af[mt][0]), "r"(af[mt][1]), "r"(af[mt][2]), "r"(af[mt][3]),
                          "r"(bf[nt][0]), "r"(bf[nt][1]));
                }
        }
    };

    constexpr int NK = (K + BK - 1) / BK;
    load_tiles(0);
    store_tiles(0);
    __syncthreads();
    for (int it = 0; it < NK; it++) {
        if (it + 1 < NK) load_tiles((it + 1) * BK);
        compute(it & 1);
        if (it + 1 < NK) store_tiles((it + 1) & 1);
        __syncthreads();
    }

#pragma unroll
    for (int mt = 0; mt < 4; mt++) {
#pragma unroll
        for (int j2 = 0; j2 < 2; j2++) {
            int m = m0 + wm + mt * 16 + r + j2 * 8;
            float scl = d_rowscale[m];
#pragma unroll
            for (int nt = 0; nt < 4; nt++) {
                int n = n0 + wn + nt * 8 + c * 2;
#pragma unroll
                for (int jj = 0; jj < 2; jj++) {
                    int nn = n + jj;
                    if (nn < N) {
                        float v = acc[mt][nt][j2 * 2 + jj] + extbias[nn];
                        v = fmaxf(v, 0.f) * scl;
                        Cout[(size_t)m * N + nn] = v;
                    }
                }
            }
        }
    }
}

// ---------------- persistent LSTM v8: barrier-hidden xv prefetch, early exit ---
#define AVCH 132
#define WS3_FLOATS (38 * 6 * AVCH)   // 30096
#define AV3_FLOATS (38 * 4 * AVCH)   // 20064
#define LSTM3_SMEM ((WS3_FLOATS + AV3_FLOATS) * 4)   // 200640

__global__ __launch_bounds__(256, 1)
void lstm_persist8() {
    extern __shared__ float sm[];
    float* Ws = sm;                  // [kb*6+np][132]
    float* Av = sm + WS3_FLOATS;     // [kb*4+mt][132]

    const int tid = threadIdx.x;
    const int lane = tid & 31, wid = tid >> 5;
    const int rt = blockIdx.x / 13, ct = blockIdx.x % 13;
    const int row0 = rt * 64, col0 = ct * 96;
    const bool bwd = (row0 >= 256);
    const float* Wt = bwd ? d_Whhb_t : d_Whhf_t;
    const float* xg = bwd ? d_xg_b : d_xg_f;

    for (int idx = tid; idx < 38 * 6 * 128; idx += 256) {
        int kb = idx / (6 * 128);
        int rem = idx - kb * 6 * 128;
        int np = rem >> 7;
        int li = rem & 127;
        int l = li >> 2, slot = li & 3;
        int atom = np * 2 + (slot >> 1);
        int col = col0 + atom * 8 + (l >> 2);
        int k = kb * 8 + (l & 3) + (slot & 1) * 4;
        float v = (k < Hx && col < G4) ? Wt[(size_t)k * G4 + col] : 0.f;
        Ws[(kb * 6 + np) * AVCH + li] = to_tf32(v);
    }
    __syncthreads();

    const int r = lane >> 2, c = lane & 3;
    const int mtw = wid & 3;
    const int nw  = wid >> 2;
    const bool evenc = ((c & 1) == 0);
    const int oddc = evenc ? 0 : 1;
    const int cpair = c >> 1;
    const int row_g = row0 + mtw * 16 + r + (evenc ? 0 : 8);
    const int b = row_g & 255;
    const int Lb = d_L[b];
    const int tEnd = d_Lmax[rt & 3];
    unsigned* barp = &d_barg[rt * 32];

    int jidx[6];
#pragma unroll
    for (int a = 0; a < 6; a++)
        jidx[a] = ((col0 + (nw * 6 + a) * 8) >> 2) + cpair;

    float cst[6] = {0.f, 0.f, 0.f, 0.f, 0.f, 0.f};

    auto mma_range = [&](float acc[6][4], int kb0, int kb1) {
#pragma unroll 2
        for (int kb = kb0; kb < kb1; kb++) {
            float4 a4 = *(const float4*)(Av + (kb * 4 + mtw) * AVCH
                                         + (((lane + kb) & 31) << 2));
            uint32_t af0 = __float_as_uint(a4.x), af1 = __float_as_uint(a4.y);
            uint32_t af2 = __float_as_uint(a4.z), af3 = __float_as_uint(a4.w);
#pragma unroll
            for (int p = 0; p < 3; p++) {
                float4 b4 = *(const float4*)(Ws + (kb * 6 + nw * 3 + p) * AVCH
                                             + (lane << 2));
                uint32_t b0 = __float_as_uint(b4.x), b1 = __float_as_uint(b4.y);
                uint32_t b2 = __float_as_uint(b4.z), b3 = __float_as_uint(b4.w);
                asm volatile(
                    "mma.sync.aligned.m16n8k8.row.col.f32.tf32.tf32.f32 "
                    "{%0,%1,%2,%3}, {%4,%5,%6,%7}, {%8,%9}, {%0,%1,%2,%3};"
                    : "+f"(acc[p*2][0]), "+f"(acc[p*2][1]),
                      "+f"(acc[p*2][2]), "+f"(acc[p*2][3])
                    : "r"(af0), "r"(af1), "r"(af2), "r"(af3), "r"(b0), "r"(b1));
                asm volatile(
                    "mma.sync.aligned.m16n8k8.row.col.f32.tf32.tf32.f32 "
                    "{%0,%1,%2,%3}, {%4,%5,%6,%7}, {%8,%9}, {%0,%1,%2,%3};"
                    : "+f"(acc[p*2+1][0]), "+f"(acc[p*2+1][1]),
                      "+f"(acc[p*2+1][2]), "+f"(acc[p*2+1][3])
                    : "r"(af0), "r"(af1), "r"(af2), "r"(af3), "r"(b2), "r"(b3));
            }
        }
    };

    auto xv_prefetch = [&](int t, float4 xv[6]) {
        int tsrc = bwd ? ((t < Lb) ? (Lb - 1 - t) : t) : t;
        const float* xgrow = xg + ((size_t)(b * Sx + tsrc)) * G4;
#pragma unroll
        for (int a = 0; a < 6; a++)
            xv[a] = (jidx[a] < Hx) ? __ldg((const float4*)(xgrow + jidx[a] * 4))
                                   : make_float4(0.f, 0.f, 0.f, 0.f);
    };

    float4 xv[6];
    xv_prefetch(0, xv);

    for (int t = 0; t < tEnd; t++) {
        const float* src = d_hf + ((size_t)((t & 1) * 8 + rt)) * 19456;
        float*       dstg = d_hf + ((size_t)(((t + 1) & 1) * 8 + rt)) * 19456;
        int pos = bwd ? ((t < Lb) ? (Lb - 1 - t) : t) : t;
        bool last = (t == tEnd - 1);

        // ---- stage part 1 (chunks 0..75 = kb 0..18) ----
        float4 h1[10];
#pragma unroll
        for (int q = 0; q < 10; q++) {
            int f = tid + 256 * q;
            h1[q] = (f < 2432) ? __ldcg((const float4*)(src + (size_t)f * 4))
                               : make_float4(0.f, 0.f, 0.f, 0.f);
        }
#pragma unroll
        for (int q = 0; q < 10; q++) {
            int f = tid + 256 * q;
            if (f < 2432) {
                int chunk = f >> 5, off = f & 31;
                *(float4*)(Av + chunk * AVCH + off * 4) = h1[q];
            }
        }
        // ---- issue part 2 loads (overlap with first MMA half) ----
        float4 h2[10];
#pragma unroll
        for (int q = 0; q < 10; q++) {
            int f = 2432 + tid + 256 * q;
            h2[q] = (f < 4864) ? __ldcg((const float4*)(src + (size_t)f * 4))
                               : make_float4(0.f, 0.f, 0.f, 0.f);
        }
        __syncthreads();

        float acc[6][4];
#pragma unroll
        for (int a = 0; a < 6; a++)
#pragma unroll
            for (int q = 0; q < 4; q++) acc[a][q] = 0.f;

        mma_range(acc, 0, 19);

#pragma unroll
        for (int q = 0; q < 10; q++) {
            int f = 2432 + tid + 256 * q;
            if (f < 4864) {
                int chunk = f >> 5, off = f & 31;
                *(float4*)(Av + chunk * AVCH + off * 4) = h2[q];
            }
        }
        __syncthreads();

        mma_range(acc, 19, 38);

        // ---- epilogue: gates, cell update, frag-major h store ----
        float hvals[6];
#pragma unroll
        for (int a = 0; a < 6; a++) {
            float d0 = acc[a][0], d1 = acc[a][1], d2 = acc[a][2], d3 = acc[a][3];
            float x0 = __shfl_xor_sync(0xFFFFFFFFu, evenc ? d2 : d0, 1);
            float x1 = __shfl_xor_sync(0xFFFFFFFFu, evenc ? d3 : d1, 1);
            float gi = evenc ? d0 : x0;
            float gf = evenc ? d1 : x1;
            float gg = evenc ? x0 : d2;
            float go = evenc ? x1 : d3;
            if (jidx[a] < Hx) {
                gi += xv[a].x; gf += xv[a].y; gg += xv[a].z; go += xv[a].w;
                float si = fsig(gi);
                float sf = fsig(gf);
                float so = fsig(go);
                float cn = sf * cst[a] + si * ftanh(gg);
                cst[a] = cn;
                hvals[a] = so * ftanh(cn);
            } else hvals[a] = 0.f;
        }
        if (!last) {
#pragma unroll
            for (int a = 0; a < 6; a++) {
                int j = jidx[a];
                if (j < Hx) {
                    int kb = j >> 3;
                    int slot = (((j >> 2) & 1) << 1) + oddc;
                    int lp = (r * 4 + (j & 3) + kb) & 31;
                    dstg[(kb * 4 + mtw) * 128 + lp * 4 + slot] = to_tf32(hvals[a]);
                }
            }
        }

        // ---- barrier with xv prefetch for t+1 hidden under the wait ----
        if (!last) {
            __syncthreads();            // h stores drained block-wide
            xv_prefetch(t + 1, xv);     // in flight during the spin
            if (tid == 0) {
                bar_release_add(barp);
                unsigned target = 13u * (unsigned)(t + 1);
                while (bar_acquire_ld(barp) < target) __nanosleep(16);
            }
            __syncthreads();
        }

        // ---- d_to stores (post-barrier; consumed only by later kernels) ----
        size_t tbase = ((size_t)(b * Sx + pos)) * Cc + (bwd ? Hx : 0);
        float mask = (t < Lb) ? 1.f : 0.f;
#pragma unroll
        for (int a = 0; a < 6; a++)
            if (jidx[a] < Hx) d_to[tbase + jidx[a]] = hvals[a] * mask;
    }
}

// ---------------- gather conv1 input windows (2 rows per batch) -----------------
__global__ void k_gatherca() {
    int rr = blockIdx.x;
    int b = rr >> 1, side = rr & 1;
    int le = d_left[b];
    int rt = le + d_asp[b] - 1;
    int p = side ? (rt + 1) : (le - 1);
    bool valid = (p >= 0 && p < Sx);
    if (threadIdx.x == 0)
        d_rowscale[rr] = valid ? d_pw[b * Sx + p] : 0.f;
    for (int k = threadIdx.x; k < KCONV; k += blockDim.x) {
        int dk = k / Cc, i = k - dk * Cc;
        int prow = p - 1 + dk;
        float val = 0.f;
        if (valid && prow >= 0 && prow < Sx)
            val = d_to[((size_t)(b * Sx + prow)) * Cc + i] * d_pw[b * Sx + prow];
        d_ca[(size_t)rr * KCONV + k] = val;
    }
}

// ---------------- conv2 on the two nonzero rows + v ----------------------------
__global__ void k_vrow(const float* __restrict__ c2bias) {
    __shared__ float s0[Cc], s1[Cc];
    int b = blockIdx.x, tid = threadIdx.x;
    int a = d_asp[b];
    for (int i = tid; i < Cc; i += blockDim.x) {
        s0[i] = d_x2row[(size_t)(b * 2 + 0) * Cc + i];
        s1[i] = d_x2row[(size_t)(b * 2 + 1) * Cc + i];
    }
    __syncthreads();
    float acc0[3] = {0.f, 0.f, 0.f}, acc1[3] = {0.f, 0.f, 0.f};
    for (int i = 0; i < Cc; i++) {
        float a0 = s0[i], a1 = s1[i];
        const float* w0 = d_cw2 + (size_t)i * Cc;
        const float* w2 = d_cw2 + (size_t)(1200 + i) * Cc;
#pragma unroll
        for (int q = 0; q < 3; q++) {
            int o = tid + q * 256;
            if (o < Cc) {
                acc0[q] = fmaf(w0[o], a0, acc0[q]);
                acc1[q] = fmaf(w2[o], a1, acc1[q]);
            }
        }
    }
#pragma unroll
    for (int q = 0; q < 3; q++) {
        int o = tid + q * 256;
        if (o < Cc) {
            float bb = c2bias[o];
            float v;
            if (a == 1) {
                v = fmaxf(acc0[q] + acc1[q] + bb, 0.f);
            } else {
                v = fmaxf(acc0[q] + bb, 0.f) + fmaxf(acc1[q] + bb, 0.f)
                  + (float)(a - 2) * fmaxf(bb, 0.f);
            }
            d_v[b * Cc + o] = v;
        }
    }
}

// ---------------- logits -------------------------------------------------------
__global__ void k_logits() {
    int b = blockIdx.x;
    int w = threadIdx.x >> 5, lane = threadIdx.x & 31;
    int t = blockIdx.y * 8 + w;
    const float* vb = d_v + (size_t)b * Cc;
    const float* to = d_to + ((size_t)(b * Sx + t)) * Cc;
    float s = 0.f;
    for (int c = lane; c < Cc; c += 32) s = fmaf(vb[c], to[c], s);
#pragma unroll
    for (int o = 16; o; o >>= 1) s += __shfl_xor_sync(0xFFFFFFFFu, s, o);
    if (lane == 0) d_logits[b * Sx + t] = s;
}

// ---------------- softmax + feat + fc ------------------------------------------
__global__ void k_final(const float* __restrict__ fcw, const float* __restrict__ fcb,
                        float* __restrict__ out) {
    __shared__ float sred[256];
    __shared__ float salpha[256];
    __shared__ float feat[Cc];
    int b = blockIdx.x, t = threadIdx.x;
    float lg = d_logits[b * Sx + t];
    sred[t] = lg;
    __syncthreads();
    for (int o = 128; o; o >>= 1) { if (t < o) sred[t] = fmaxf(sred[t], sred[t + o]); __syncthreads(); }
    float mx = sred[0];
    __syncthreads();
    float e = expf(lg - mx);
    salpha[t] = e;
    sred[t] = e;
    __syncthreads();
    for (int o = 128; o; o >>= 1) { if (t < o) sred[t] += sred[t + o]; __syncthreads(); }
    float Z = sred[0];
    __syncthreads();
    for (int c = t; c < Cc; c += 256) {
        float f = 0.f;
        for (int tt = 0; tt < Sx; tt++)
            f = fmaf(salpha[tt], d_to[((size_t)(b * Sx + tt)) * Cc + c], f);
        feat[c] = f / Z;
    }
    __syncthreads();
    for (int p = 0; p < 3; p++) {
        float part = 0.f;
        for (int c = t; c < Cc; c += 256) part = fmaf(feat[c], fcw[p * Cc + c], part);
        sred[t] = part;
        __syncthreads();
        for (int o = 128; o; o >>= 1) { if (t < o) sred[t] += sred[t + o]; __syncthreads(); }
        if (t == 0) out[b * 3 + p] = sred[0] + fcb[p];
        __syncthreads();
    }
}

// ---------------- launch -------------------------------------------------------
extern "C" void kernel_launch(void* const* d_in, const int* in_sizes, int n_in,
                              void* d_out, int out_size) {
    (void)in_sizes; (void)n_in; (void)out_size;
    const int*   cat   = (const int*)d_in[0];
    const int*   aspi  = (const int*)d_in[1];
    const int*   lefti = (const int*)d_in[2];
    const float* emb   = (const float*)d_in[3];
    const float* Wihf  = (const float*)d_in[4];
    const float* Whhf  = (const float*)d_in[5];
    const float* bf    = (const float*)d_in[6];
    const float* Wihb  = (const float*)d_in[7];
    const float* Whhb  = (const float*)d_in[8];
    const float* bbv   = (const float*)d_in[9];
    const float* c1w   = (const float*)d_in[10];
    const float* c1b   = (const float*)d_in[11];
    const float* c2w   = (const float*)d_in[12];
    const float* c2b   = (const float*)d_in[13];
    const float* fcw   = (const float*)d_in[14];
    const float* fcb   = (const float*)d_in[15];
    float* out = (float*)d_out;

    cudaFuncSetAttribute(lstm_persist8, cudaFuncAttributeMaxDynamicSharedMemorySize,
                         LSTM3_SMEM);

    k_meta<<<Bx, 256>>>(cat, aspi, lefti);
    k_zero<<<512, 256>>>();
    k_prep<<<2048, 256>>>(Wihf, Whhf, bf, Wihb, Whhb, bbv, c1w, c2w);

    dim3 g1(19, 512);   // N=2400, M=65536
    xg_gemm<<<g1, 256>>>(cat, emb);

    lstm_persist8<<<104, 256, LSTM3_SMEM>>>();

    k_gatherca<<<512, 256>>>();
    dim3 g2(5, 4);      // N=600, M=512
    conv_gemm<<<g2, 256>>>(c1b);
    k_vrow<<<Bx, 256>>>(c2b);

    dim3 g3(Bx, 32);
    k_logits<<<g3, 256>>>();
    k_final<<<Bx, 256>>>(fcw, fcb, out);
}

// round 17
// speedup vs baseline: 1.1156x; 1.0227x over previous
#include <cuda_runtime.h>
#include <stdint.h>
#include <math.h>

#define Bx 256
#define Sx 256
#define Ex 300
#define Hx 300
#define G4 1200     // 4*H
#define Cc 600      // 2*H channels
#define Mx 65536    // B*S
#define KCONV 1800  // 3*Cc

// ---------------- scratch (__device__ globals; zero-init at load) -------------
__device__ float d_xg_f[(size_t)Mx * G4];
__device__ float d_xg_b[(size_t)Mx * G4];
__device__ float d_to[(size_t)Mx * Cc];
// frag-major h ping-pong: [buf][group][152 chunks][128]  (152*128 = 19456)
__device__ float d_hf[2 * 8 * 19456];
__device__ float d_Whhf_t[Hx * G4];             // [k][j*4+g]
__device__ float d_Whhb_t[Hx * G4];
// fused input weights, tf32, fragment-major: [38 slabs][150 pairs][128]
__device__ float d_Wfrag[38 * 150 * 128];
__device__ float d_bif[G4];
__device__ float d_bib[G4];
__device__ float d_cw1[KCONV * Cc];
__device__ float d_cw2[KCONV * Cc];
__device__ float d_pw[Mx];
__device__ int   d_L[Bx], d_asp[Bx], d_left[Bx];
__device__ int   d_Lmax[4];                     // max L per 64-batch group
__device__ float d_ca[512 * KCONV];
__device__ float d_x2row[512 * Cc];
__device__ float d_rowscale[512];
__device__ float d_v[Bx * Cc];
__device__ unsigned d_barg[8 * 32];             // one counter per 128B line

__device__ __forceinline__ float to_tf32(float x) {
    uint32_t r;
    asm("cvt.rna.tf32.f32 %0, %1;" : "=r"(r) : "f"(x));
    return __uint_as_float(r);
}
__device__ __forceinline__ float fsig(float x) {
    return __fdividef(1.f, 1.f + __expf(-x));
}
__device__ __forceinline__ float ftanh(float x) {
    return __fdividef(2.f, 1.f + __expf(-2.f * x)) - 1.f;
}
__device__ __forceinline__ void bar_release_add(unsigned* p) {
    asm volatile("red.add.release.gpu.u32 [%0], 1;" :: "l"(p) : "memory");
}
__device__ __forceinline__ unsigned bar_acquire_ld(unsigned* p) {
    unsigned v;
    asm volatile("ld.acquire.gpu.u32 %0, [%1];" : "=r"(v) : "l"(p) : "memory");
    return v;
}

// ---------------- meta ---------------------------------------------------------
__global__ void k_meta(const int* __restrict__ cat, const int* __restrict__ aspi,
                       const int* __restrict__ lefti) {
    __shared__ int s[3];
    int b = blockIdx.x, t = threadIdx.x;
    if (t < 3) s[t] = 0;
    __syncthreads();
    if (cat[b * Sx + t] != 0) atomicAdd(&s[0], 1);
    if (t < 16 && aspi[b * 16 + t] != 0) atomicAdd(&s[1], 1);
    if (t < 128 && lefti[b * 128 + t] != 0) atomicAdd(&s[2], 1);
    __syncthreads();
    int L = s[0], A = s[1], Le = s[2];
    if (t == 0) {
        d_L[b] = L; d_asp[b] = A; d_left[b] = Le;
        atomicMax(&d_Lmax[b >> 6], L);
    }
    float na = (float)(L - A);
    int right = Le + A - 1;
    float w;
    if (t < Le)           w = 1.0f - (float)(Le - t) / na;
    else if (t <= right)  w = 0.0f;
    else if (t < L)       w = 1.0f - (float)(t - right) / na;
    else                  w = 0.0f;
    d_pw[b * Sx + t] = w;
}

// ---------------- zero h buffer 0 + group barrier counters ---------------------
__global__ void k_zero() {
    int stride = gridDim.x * blockDim.x;
    int tid0 = blockIdx.x * blockDim.x + threadIdx.x;
    for (int i = tid0; i < 8 * 19456; i += stride) d_hf[i] = 0.f;
    if (tid0 < 8 * 32) d_barg[tid0] = 0u;
}

// ---------------- weight reshapes ----------------------------------------------
__global__ void k_prep(const float* __restrict__ Wihf, const float* __restrict__ Whhf,
                       const float* __restrict__ bf,
                       const float* __restrict__ Wihb, const float* __restrict__ Whhb,
                       const float* __restrict__ bbv,
                       const float* __restrict__ c1w, const float* __restrict__ c2w) {
    int stride = gridDim.x * blockDim.x;
    int tid0 = blockIdx.x * blockDim.x + threadIdx.x;
    for (int idx = tid0; idx < Ex * G4; idx += stride) {
        int k = idx / G4, col = idx - k * G4;
        int j = col >> 2, g = col & 3;
        int src = (g * Hx + j) * Ex + k;   // Ex == Hx
        d_Whhf_t[idx] = Whhf[src];
        d_Whhb_t[idx] = Whhb[src];
    }
    for (int idx = tid0; idx < 38 * 150 * 128; idx += stride) {
        int kb = idx / 19200;
        int rem = idx - kb * 19200;
        int np = rem >> 7;
        int li = rem & 127;
        int l = li >> 2, slot = li & 3;
        int atom = np * 2 + (slot >> 1);
        int col = atom * 8 + (l >> 2);
        int k = kb * 8 + (l & 3) + ((slot & 1) << 2);
        float v = 0.f;
        if (k < Ex) {
            int colp = (col < G4) ? col : col - G4;
            const float* W = (col < G4) ? Wihf : Wihb;
            int j = colp >> 2, g = colp & 3;
            v = W[(g * Hx + j) * Ex + k];
        }
        d_Wfrag[idx] = to_tf32(v);
    }
    for (int idx = tid0; idx < G4; idx += stride) {
        int j = idx >> 2, g = idx & 3;
        d_bif[idx] = bf[g * Hx + j];
        d_bib[idx] = bbv[g * Hx + j];
    }
    // conv weights: iterate SOURCE-linear (coalesced reads, scattered writes)
    for (int idx = tid0; idx < KCONV * Cc; idx += stride) {
        int o = idx / KCONV;               // source row (output channel)
        int rem = idx - o * KCONV;         // i*3 + kk
        int i = rem / 3, kk = rem - i * 3;
        size_t dst = (size_t)(kk * Cc + i) * Cc + o;
        d_cw1[dst] = c1w[idx];
        d_cw2[dst] = c2w[idx];
    }
}

// ---------------- xg GEMM (R12 version + dead-tile skip + streaming stores) ----
#define LDSW 136
__global__ __launch_bounds__(256, 2)
void xg_gemm(const int* __restrict__ cat, const float* __restrict__ emb) {
    __shared__ float As[2][16][LDSW];

    int m0 = blockIdx.y * 128;
    if ((m0 & 255) == 128 && d_L[m0 >> 8] <= 128) return;

    int tid = threadIdx.x;
    int lane = tid & 31, wid = tid >> 5;
    int wm = (wid & 1) * 64;
    int wn = (wid >> 1) * 32;
    int n0 = blockIdx.x * 128;
    int npg = (n0 + wn) >> 4;

    size_t abase[2]; int arow[2], akq[2];
#pragma unroll
    for (int q = 0; q < 2; q++) {
        int pos = tid + 256 * q;
        arow[q] = pos >> 2;
        akq[q]  = (pos & 3) * 4;
        abase[q] = (size_t)cat[m0 + arow[q]] * Ex;
    }

    float4 ra[2];
    auto loadA = [&](int k0) {
#pragma unroll
        for (int q = 0; q < 2; q++) {
            int k = k0 + akq[q];
            ra[q] = (k < Ex) ? *(const float4*)(emb + abase[q] + k)
                             : make_float4(0.f, 0.f, 0.f, 0.f);
        }
    };
    auto storeA = [&](int s) {
#pragma unroll
        for (int q = 0; q < 2; q++) {
            As[s][akq[q] + 0][arow[q]] = to_tf32(ra[q].x);
            As[s][akq[q] + 1][arow[q]] = to_tf32(ra[q].y);
            As[s][akq[q] + 2][arow[q]] = to_tf32(ra[q].z);
            As[s][akq[q] + 3][arow[q]] = to_tf32(ra[q].w);
        }
    };

    float4 breg[2][2];
    auto loadB = [&](int kbg, float4 bp[2]) {
#pragma unroll
        for (int p = 0; p < 2; p++) {
            int np = npg + p;
            bp[p] = (np < 150)
                ? __ldg((const float4*)(d_Wfrag + ((size_t)kbg * 150 + np) * 128 + lane * 4))
                : make_float4(0.f, 0.f, 0.f, 0.f);
        }
    };

    float acc[4][4][4];
#pragma unroll
    for (int i = 0; i < 4; i++)
#pragma unroll
        for (int j = 0; j < 4; j++)
#pragma unroll
            for (int q = 0; q < 4; q++) acc[i][j][q] = 0.f;

    int r = lane >> 2, c = lane & 3;

    loadA(0); storeA(0);
    loadB(0, breg[0]);
    __syncthreads();

    for (int it = 0; it < 19; it++) {
        if (it + 1 < 19) loadA((it + 1) * 16);
#pragma unroll
        for (int ks = 0; ks < 2; ks++) {
            int kbg = it * 2 + ks;
            if (kbg + 1 < 38) loadB(kbg + 1, breg[(kbg + 1) & 1]);
            int kb = ks * 8;
            int s = it & 1;
            uint32_t af[4][4];
#pragma unroll
            for (int mt = 0; mt < 4; mt++) {
                int mb = wm + mt * 16 + r;
                af[mt][0] = __float_as_uint(As[s][kb + c][mb]);
                af[mt][1] = __float_as_uint(As[s][kb + c][mb + 8]);
                af[mt][2] = __float_as_uint(As[s][kb + c + 4][mb]);
                af[mt][3] = __float_as_uint(As[s][kb + c + 4][mb + 8]);
            }
            float4* bp = breg[kbg & 1];
            uint32_t bf[4][2];
#pragma unroll
            for (int p = 0; p < 2; p++) {
                bf[p * 2 + 0][0] = __float_as_uint(bp[p].x);
                bf[p * 2 + 0][1] = __float_as_uint(bp[p].y);
                bf[p * 2 + 1][0] = __float_as_uint(bp[p].z);
                bf[p * 2 + 1][1] = __float_as_uint(bp[p].w);
            }
#pragma unroll
            for (int mt = 0; mt < 4; mt++)
#pragma unroll
                for (int nt = 0; nt < 4; nt++) {
                    asm volatile(
                        "mma.sync.aligned.m16n8k8.row.col.f32.tf32.tf32.f32 "
                        "{%0,%1,%2,%3}, {%4,%5,%6,%7}, {%8,%9}, {%0,%1,%2,%3};"
                        : "+f"(acc[mt][nt][0]), "+f"(acc[mt][nt][1]),
                          "+f"(acc[mt][nt][2]), "+f"(acc[mt][nt][3])
                        : "r"(af[mt][0]), "r"(af[mt][1]), "r"(af[mt][2]), "r"(af[mt][3]),
                          "r"(bf[nt][0]), "r"(bf[nt][1]));
                }
        }
        if (it + 1 < 19) storeA((it + 1) & 1);
        __syncthreads();
    }

#pragma unroll
    for (int mt = 0; mt < 4; mt++) {
#pragma unroll
        for (int j2 = 0; j2 < 2; j2++) {
            int m = m0 + wm + mt * 16 + r + j2 * 8;
#pragma unroll
            for (int nt = 0; nt < 4; nt++) {
                int n = n0 + wn + (nt >> 1) * 16 + (nt & 1) * 8 + c * 2;
#pragma unroll
                for (int jj = 0; jj < 2; jj++) {
                    int nn = n + jj;
                    float v = acc[mt][nt][j2 * 2 + jj];
                    if (nn < G4)
                        __stcs(&d_xg_f[(size_t)m * G4 + nn], v + d_bif[nn]);
                    else if (nn < 2400)
                        __stcs(&d_xg_b[(size_t)m * G4 + (nn - G4)], v + d_bib[nn - G4]);
                }
            }
        }
    }
}

// ---------------- conv1 GEMM (proven template) ---------------------------------
__global__ __launch_bounds__(256, 2)
void conv_gemm(const float* __restrict__ extbias) {
    constexpr int N = Cc, K = KCONV, BK = 16;
    const float* A = d_ca;
    const float* Bw = d_cw1;
    float* Cout = d_x2row;

    __shared__ float As[2][BK][LDSW];
    __shared__ float Bs[2][BK][LDSW];

    int tid = threadIdx.x;
    int lane = tid & 31, wid = tid >> 5;
    int wm = (wid & 1) * 64;
    int wn = (wid >> 1) * 32;
    int m0 = blockIdx.y * 128, n0 = blockIdx.x * 128;

    size_t abase[2]; int arow[2], akq[2];
    int bkr[2], bnq[2];
#pragma unroll
    for (int q = 0; q < 2; q++) {
        int pos = tid + 256 * q;
        arow[q] = pos >> 2;
        akq[q]  = (pos & 3) * 4;
        abase[q] = (size_t)(m0 + arow[q]) * K;
        bkr[q] = pos >> 5;
        bnq[q] = (pos & 31) * 4;
    }

    float4 ra[2], rb[2];
    auto load_tiles = [&](int k0) {
#pragma unroll
        for (int q = 0; q < 2; q++) {
            int k = k0 + akq[q];
            ra[q] = (k < K) ? *(const float4*)(A + abase[q] + k)
                            : make_float4(0.f, 0.f, 0.f, 0.f);
            int kb = k0 + bkr[q], n = n0 + bnq[q];
            rb[q] = (kb < K && n < N) ? *(const float4*)(Bw + (size_t)kb * N + n)
                                      : make_float4(0.f, 0.f, 0.f, 0.f);
        }
    };
    auto store_tiles = [&](int s) {
#pragma unroll
        for (int q = 0; q < 2; q++) {
            As[s][akq[q] + 0][arow[q]] = to_tf32(ra[q].x);
            As[s][akq[q] + 1][arow[q]] = to_tf32(ra[q].y);
            As[s][akq[q] + 2][arow[q]] = to_tf32(ra[q].z);
            As[s][akq[q] + 3][arow[q]] = to_tf32(ra[q].w);
            Bs[s][bkr[q]][bnq[q] + 0] = to_tf32(rb[q].x);
            Bs[s][bkr[q]][bnq[q] + 1] = to_tf32(rb[q].y);
            Bs[s][bkr[q]][bnq[q] + 2] = to_tf32(rb[q].z);
            Bs[s][bkr[q]][bnq[q] + 3] = to_tf32(rb[q].w);
        }
    };

    float acc[4][4][4];
#pragma unroll
    for (int i = 0; i < 4; i++)
#pragma unroll
        for (int j = 0; j < 4; j++)
#pragma unroll
            for (int q = 0; q < 4; q++) acc[i][j][q] = 0.f;

    int r = lane >> 2, c = lane & 3;

    auto compute = [&](int s) {
#pragma unroll
        for (int ks = 0; ks < 2; ks++) {
            int kb = ks * 8;
            uint32_t af[4][4], bf[4][2];
#pragma unroll
            for (int mt = 0; mt < 4; mt++) {
                int mb = wm + mt * 16 + r;
                af[mt][0] = __float_as_uint(As[s][kb + c][mb]);
                af[mt][1] = __float_as_uint(As[s][kb + c][mb + 8]);
                af[mt][2] = __float_as_uint(As[s][kb + c + 4][mb]);
                af[mt][3] = __float_as_uint(As[s][kb + c + 4][mb + 8]);
            }
#pragma unroll
            for (int nt = 0; nt < 4; nt++) {
                int nb = wn + nt * 8 + r;
                bf[nt][0] = __float_as_uint(Bs[s][kb + c][nb]);
                bf[nt][1] = __float_as_uint(Bs[s][kb + c + 4][nb]);
            }
#pragma unroll
            for (int mt = 0; mt < 4; mt++)
#pragma unroll
                for (int nt = 0; nt < 4; nt++) {
                    asm volatile(
                        "mma.sync.aligned.m16n8k8.row.col.f32.tf32.tf32.f32 "
                        "{%0,%1,%2,%3}, {%4,%5,%6,%7}, {%8,%9}, {%0,%1,%2,%3};"
                        : "+f"(acc[mt][nt][0]), "+f"(acc[mt][nt][1]),
                          "+f"(acc[mt][nt][2]), "+f"(acc[mt][nt][3])
                        : "r"(af[mt][0]), "r"(af[mt][1]), "r"(af[mt][2]), "r"(af[mt][3]),
                          "r"(bf[nt][0]), "r"(bf[nt][1]));
                }
        }
    };

    constexpr int NK = (K + BK - 1) / BK;
    load_tiles(0);
    store_tiles(0);
    __syncthreads();
    for (int it = 0; it < NK; it++) {
        if (it + 1 < NK) load_tiles((it + 1) * BK);
        compute(it & 1);
        if (it + 1 < NK) store_tiles((it + 1) & 1);
        __syncthreads();
    }

#pragma unroll
    for (int mt = 0; mt < 4; mt++) {
#pragma unroll
        for (int j2 = 0; j2 < 2; j2++) {
            int m = m0 + wm + mt * 16 + r + j2 * 8;
            float scl = d_rowscale[m];
#pragma unroll
            for (int nt = 0; nt < 4; nt++) {
                int n = n0 + wn + nt * 8 + c * 2;
#pragma unroll
                for (int jj = 0; jj < 2; jj++) {
                    int nn = n + jj;
                    if (nn < N) {
                        float v = acc[mt][nt][j2 * 2 + jj] + extbias[nn];
                        v = fmaxf(v, 0.f) * scl;
                        Cout[(size_t)m * N + nn] = v;
                    }
                }
            }
        }
    }
}

// ---------------- persistent LSTM v8 (R16 champion) ----------------------------
#define AVCH 132
#define WS3_FLOATS (38 * 6 * AVCH)   // 30096
#define AV3_FLOATS (38 * 4 * AVCH)   // 20064
#define LSTM3_SMEM ((WS3_FLOATS + AV3_FLOATS) * 4)   // 200640

__global__ __launch_bounds__(256, 1)
void lstm_persist8() {
    extern __shared__ float sm[];
    float* Ws = sm;
    float* Av = sm + WS3_FLOATS;

    const int tid = threadIdx.x;
    const int lane = tid & 31, wid = tid >> 5;
    const int rt = blockIdx.x / 13, ct = blockIdx.x % 13;
    const int row0 = rt * 64, col0 = ct * 96;
    const bool bwd = (row0 >= 256);
    const float* Wt = bwd ? d_Whhb_t : d_Whhf_t;
    const float* xg = bwd ? d_xg_b : d_xg_f;

    for (int idx = tid; idx < 38 * 6 * 128; idx += 256) {
        int kb = idx / (6 * 128);
        int rem = idx - kb * 6 * 128;
        int np = rem >> 7;
        int li = rem & 127;
        int l = li >> 2, slot = li & 3;
        int atom = np * 2 + (slot >> 1);
        int col = col0 + atom * 8 + (l >> 2);
        int k = kb * 8 + (l & 3) + (slot & 1) * 4;
        float v = (k < Hx && col < G4) ? Wt[(size_t)k * G4 + col] : 0.f;
        Ws[(kb * 6 + np) * AVCH + li] = to_tf32(v);
    }
    __syncthreads();

    const int r = lane >> 2, c = lane & 3;
    const int mtw = wid & 3;
    const int nw  = wid >> 2;
    const bool evenc = ((c & 1) == 0);
    const int oddc = evenc ? 0 : 1;
    const int cpair = c >> 1;
    const int row_g = row0 + mtw * 16 + r + (evenc ? 0 : 8);
    const int b = row_g & 255;
    const int Lb = d_L[b];
    const int tEnd = d_Lmax[rt & 3];
    unsigned* barp = &d_barg[rt * 32];

    int jidx[6];
#pragma unroll
    for (int a = 0; a < 6; a++)
        jidx[a] = ((col0 + (nw * 6 + a) * 8) >> 2) + cpair;

    float cst[6] = {0.f, 0.f, 0.f, 0.f, 0.f, 0.f};

    auto mma_range = [&](float acc[6][4], int kb0, int kb1) {
#pragma unroll 2
        for (int kb = kb0; kb < kb1; kb++) {
            float4 a4 = *(const float4*)(Av + (kb * 4 + mtw) * AVCH
                                         + (((lane + kb) & 31) << 2));
            uint32_t af0 = __float_as_uint(a4.x), af1 = __float_as_uint(a4.y);
            uint32_t af2 = __float_as_uint(a4.z), af3 = __float_as_uint(a4.w);
#pragma unroll
            for (int p = 0; p < 3; p++) {
                float4 b4 = *(const float4*)(Ws + (kb * 6 + nw * 3 + p) * AVCH
                                             + (lane << 2));
                uint32_t b0 = __float_as_uint(b4.x), b1 = __float_as_uint(b4.y);
                uint32_t b2 = __float_as_uint(b4.z), b3 = __float_as_uint(b4.w);
                asm volatile(
                    "mma.sync.aligned.m16n8k8.row.col.f32.tf32.tf32.f32 "
                    "{%0,%1,%2,%3}, {%4,%5,%6,%7}, {%8,%9}, {%0,%1,%2,%3};"
                    : "+f"(acc[p*2][0]), "+f"(acc[p*2][1]),
                      "+f"(acc[p*2][2]), "+f"(acc[p*2][3])
                    : "r"(af0), "r"(af1), "r"(af2), "r"(af3), "r"(b0), "r"(b1));
                asm volatile(
                    "mma.sync.aligned.m16n8k8.row.col.f32.tf32.tf32.f32 "
                    "{%0,%1,%2,%3}, {%4,%5,%6,%7}, {%8,%9}, {%0,%1,%2,%3};"
                    : "+f"(acc[p*2+1][0]), "+f"(acc[p*2+1][1]),
                      "+f"(acc[p*2+1][2]), "+f"(acc[p*2+1][3])
                    : "r"(af0), "r"(af1), "r"(af2), "r"(af3), "r"(b2), "r"(b3));
            }
        }
    };

    auto xv_prefetch = [&](int t, float4 xv[6]) {
        int tsrc = bwd ? ((t < Lb) ? (Lb - 1 - t) : t) : t;
        const float* xgrow = xg + ((size_t)(b * Sx + tsrc)) * G4;
#pragma unroll
        for (int a = 0; a < 6; a++)
            xv[a] = (jidx[a] < Hx) ? __ldg((const float4*)(xgrow + jidx[a] * 4))
                                   : make_float4(0.f, 0.f, 0.f, 0.f);
    };

    float4 xv[6];
    xv_prefetch(0, xv);

    for (int t = 0; t < tEnd; t++) {
        const float* src = d_hf + ((size_t)((t & 1) * 8 + rt)) * 19456;
        float*       dstg = d_hf + ((size_t)(((t + 1) & 1) * 8 + rt)) * 19456;
        int pos = bwd ? ((t < Lb) ? (Lb - 1 - t) : t) : t;
        bool last = (t == tEnd - 1);

        float4 h1[10];
#pragma unroll
        for (int q = 0; q < 10; q++) {
            int f = tid + 256 * q;
            h1[q] = (f < 2432) ? __ldcg((const float4*)(src + (size_t)f * 4))
                               : make_float4(0.f, 0.f, 0.f, 0.f);
        }
#pragma unroll
        for (int q = 0; q < 10; q++) {
            int f = tid + 256 * q;
            if (f < 2432) {
                int chunk = f >> 5, off = f & 31;
                *(float4*)(Av + chunk * AVCH + off * 4) = h1[q];
            }
        }
        float4 h2[10];
#pragma unroll
        for (int q = 0; q < 10; q++) {
            int f = 2432 + tid + 256 * q;
            h2[q] = (f < 4864) ? __ldcg((const float4*)(src + (size_t)f * 4))
                               : make_float4(0.f, 0.f, 0.f, 0.f);
        }
        __syncthreads();

        float acc[6][4];
#pragma unroll
        for (int a = 0; a < 6; a++)
#pragma unroll
            for (int q = 0; q < 4; q++) acc[a][q] = 0.f;

        mma_range(acc, 0, 19);

#pragma unroll
        for (int q = 0; q < 10; q++) {
            int f = 2432 + tid + 256 * q;
            if (f < 4864) {
                int chunk = f >> 5, off = f & 31;
                *(float4*)(Av + chunk * AVCH + off * 4) = h2[q];
            }
        }
        __syncthreads();

        mma_range(acc, 19, 38);

        float hvals[6];
#pragma unroll
        for (int a = 0; a < 6; a++) {
            float d0 = acc[a][0], d1 = acc[a][1], d2 = acc[a][2], d3 = acc[a][3];
            float x0 = __shfl_xor_sync(0xFFFFFFFFu, evenc ? d2 : d0, 1);
            float x1 = __shfl_xor_sync(0xFFFFFFFFu, evenc ? d3 : d1, 1);
            float gi = evenc ? d0 : x0;
            float gf = evenc ? d1 : x1;
            float gg = evenc ? x0 : d2;
            float go = evenc ? x1 : d3;
            if (jidx[a] < Hx) {
                gi += xv[a].x; gf += xv[a].y; gg += xv[a].z; go += xv[a].w;
                float si = fsig(gi);
                float sf = fsig(gf);
                float so = fsig(go);
                float cn = sf * cst[a] + si * ftanh(gg);
                cst[a] = cn;
                hvals[a] = so * ftanh(cn);
            } else hvals[a] = 0.f;
        }
        if (!last) {
#pragma unroll
            for (int a = 0; a < 6; a++) {
                int j = jidx[a];
                if (j < Hx) {
                    int kb = j >> 3;
                    int slot = (((j >> 2) & 1) << 1) + oddc;
                    int lp = (r * 4 + (j & 3) + kb) & 31;
                    dstg[(kb * 4 + mtw) * 128 + lp * 4 + slot] = to_tf32(hvals[a]);
                }
            }
        }

        if (!last) {
            __syncthreads();
            xv_prefetch(t + 1, xv);
            if (tid == 0) {
                bar_release_add(barp);
                unsigned target = 13u * (unsigned)(t + 1);
                while (bar_acquire_ld(barp) < target) __nanosleep(16);
            }
            __syncthreads();
        }

        size_t tbase = ((size_t)(b * Sx + pos)) * Cc + (bwd ? Hx : 0);
        float mask = (t < Lb) ? 1.f : 0.f;
#pragma unroll
        for (int a = 0; a < 6; a++)
            if (jidx[a] < Hx) d_to[tbase + jidx[a]] = hvals[a] * mask;
    }
}

// ---------------- gather conv1 input windows (2 rows per batch) -----------------
__global__ void k_gatherca() {
    int rr = blockIdx.x;
    int b = rr >> 1, side = rr & 1;
    int le = d_left[b];
    int rt = le + d_asp[b] - 1;
    int p = side ? (rt + 1) : (le - 1);
    bool valid = (p >= 0 && p < Sx);
    if (threadIdx.x == 0)
        d_rowscale[rr] = valid ? d_pw[b * Sx + p] : 0.f;
    for (int k = threadIdx.x; k < KCONV; k += blockDim.x) {
        int dk = k / Cc, i = k - dk * Cc;
        int prow = p - 1 + dk;
        float val = 0.f;
        if (valid && prow >= 0 && prow < Sx)
            val = d_to[((size_t)(b * Sx + prow)) * Cc + i] * d_pw[b * Sx + prow];
        d_ca[(size_t)rr * KCONV + k] = val;
    }
}

// ---------------- conv2 on the two nonzero rows + v ----------------------------
__global__ void k_vrow(const float* __restrict__ c2bias) {
    __shared__ float s0[Cc], s1[Cc];
    int b = blockIdx.x, tid = threadIdx.x;
    int a = d_asp[b];
    for (int i = tid; i < Cc; i += blockDim.x) {
        s0[i] = d_x2row[(size_t)(b * 2 + 0) * Cc + i];
        s1[i] = d_x2row[(size_t)(b * 2 + 1) * Cc + i];
    }
    __syncthreads();
    float acc0[3] = {0.f, 0.f, 0.f}, acc1[3] = {0.f, 0.f, 0.f};
    for (int i = 0; i < Cc; i++) {
        float a0 = s0[i], a1 = s1[i];
        const float* w0 = d_cw2 + (size_t)i * Cc;
        const float* w2 = d_cw2 + (size_t)(1200 + i) * Cc;
#pragma unroll
        for (int q = 0; q < 3; q++) {
            int o = tid + q * 256;
            if (o < Cc) {
                acc0[q] = fmaf(w0[o], a0, acc0[q]);
                acc1[q] = fmaf(w2[o], a1, acc1[q]);
            }
        }
    }
#pragma unroll
    for (int q = 0; q < 3; q++) {
        int o = tid + q * 256;
        if (o < Cc) {
            float bb = c2bias[o];
            float v;
            if (a == 1) {
                v = fmaxf(acc0[q] + acc1[q] + bb, 0.f);
            } else {
                v = fmaxf(acc0[q] + bb, 0.f) + fmaxf(acc1[q] + bb, 0.f)
                  + (float)(a - 2) * fmaxf(bb, 0.f);
            }
            d_v[b * Cc + o] = v;
        }
    }
}

// ---------------- fused attention tail: logits + softmax + feat + fc -----------
__global__ __launch_bounds__(256, 4)
void k_attn(const float* __restrict__ fcw, const float* __restrict__ fcb,
            float* __restrict__ out) {
    __shared__ float slog[256];
    __shared__ float sred[256];
    __shared__ float feat[Cc];
    int b = blockIdx.x, tid = threadIdx.x;
    int w = tid >> 5, lane = tid & 31;
    const float* vb = d_v + (size_t)b * Cc;
    const float* tob = d_to + (size_t)b * Sx * Cc;

    // phase 1: logits for all 256 positions (8 warps x 32 t each)
    for (int ti = 0; ti < 32; ti++) {
        int t = w * 32 + ti;
        const float* to = tob + (size_t)t * Cc;
        float s = 0.f;
        for (int cc = lane; cc < Cc; cc += 32) s = fmaf(vb[cc], to[cc], s);
#pragma unroll
        for (int o = 16; o; o >>= 1) s += __shfl_xor_sync(0xFFFFFFFFu, s, o);
        if (lane == 0) slog[t] = s;
    }
    __syncthreads();

    // phase 2: softmax over 256
    float lg = slog[tid];
    sred[tid] = lg;
    __syncthreads();
    for (int o = 128; o; o >>= 1) { if (tid < o) sred[tid] = fmaxf(sred[tid], sred[tid + o]); __syncthreads(); }
    float mx = sred[0];
    __syncthreads();
    float e = expf(lg - mx);
    slog[tid] = e;
    sred[tid] = e;
    __syncthreads();
    for (int o = 128; o; o >>= 1) { if (tid < o) sred[tid] += sred[tid + o]; __syncthreads(); }
    float Z = sred[0];
    __syncthreads();

    // phase 3: feat
    for (int cc = tid; cc < Cc; cc += 256) {
        float f = 0.f;
        for (int tt = 0; tt < Sx; tt++)
            f = fmaf(slog[tt], tob[(size_t)tt * Cc + cc], f);
        feat[cc] = f / Z;
    }
    __syncthreads();

    // phase 4: fc (3 outputs)
    for (int p = 0; p < 3; p++) {
        float part = 0.f;
        for (int cc = tid; cc < Cc; cc += 256) part = fmaf(feat[cc], fcw[p * Cc + cc], part);
        sred[tid] = part;
        __syncthreads();
        for (int o = 128; o; o >>= 1) { if (tid < o) sred[tid] += sred[tid + o]; __syncthreads(); }
        if (tid == 0) out[b * 3 + p] = sred[0] + fcb[p];
        __syncthreads();
    }
}

// ---------------- launch -------------------------------------------------------
extern "C" void kernel_launch(void* const* d_in, const int* in_sizes, int n_in,
                              void* d_out, int out_size) {
    (void)in_sizes; (void)n_in; (void)out_size;
    const int*   cat   = (const int*)d_in[0];
    const int*   aspi  = (const int*)d_in[1];
    const int*   lefti = (const int*)d_in[2];
    const float* emb   = (const float*)d_in[3];
    const float* Wihf  = (const float*)d_in[4];
    const float* Whhf  = (const float*)d_in[5];
    const float* bf    = (const float*)d_in[6];
    const float* Wihb  = (const float*)d_in[7];
    const float* Whhb  = (const float*)d_in[8];
    const float* bbv   = (const float*)d_in[9];
    const float* c1w   = (const float*)d_in[10];
    const float* c1b   = (const float*)d_in[11];
    const float* c2w   = (const float*)d_in[12];
    const float* c2b   = (const float*)d_in[13];
    const float* fcw   = (const float*)d_in[14];
    const float* fcb   = (const float*)d_in[15];
    float* out = (float*)d_out;

    cudaFuncSetAttribute(lstm_persist8, cudaFuncAttributeMaxDynamicSharedMemorySize,
                         LSTM3_SMEM);

    k_meta<<<Bx, 256>>>(cat, aspi, lefti);
    k_zero<<<512, 256>>>();
    k_prep<<<2048, 256>>>(Wihf, Whhf, bf, Wihb, Whhb, bbv, c1w, c2w);

    dim3 g1(19, 512);   // N=2400, M=65536
    xg_gemm<<<g1, 256>>>(cat, emb);

    lstm_persist8<<<104, 256, LSTM3_SMEM>>>();

    k_gatherca<<<512, 256>>>();
    dim3 g2(5, 4);      // N=600, M=512
    conv_gemm<<<g2, 256>>>(c1b);
    k_vrow<<<Bx, 256>>>(c2b);

    k_attn<<<Bx, 256>>>(fcw, fcb, out);
}